// round 1
// baseline (speedup 1.0000x reference)
#include <cuda_runtime.h>
#include <cuda_bf16.h>
#include <math.h>

// Problem constants
#define Bb   8
#define Ss   1024
#define Dd   1024
#define Hh   16
#define HD   64
#define Nn   16
#define TOK  (Bb*Ss)          // 8192
#define ELEM ((size_t)Bb*Ss*Dd) // 8388608

// Scratch (allocation-free rule: device globals)
__device__ float g_q[ELEM];
__device__ float g_attn[ELEM];

// ---------------------------------------------------------------------------
// SGEMM: C[M,Nc] = A[M,K] @ W[K,Nc], fp32. 128x128 tile, BK=8, 256 thr, 8x8/thr
// ---------------------------------------------------------------------------
#define BM 128
#define BN 128
#define BKt 8
#define TM 8
#define TN 8

__global__ __launch_bounds__(256) void sgemm_kernel(
    const float* __restrict__ A, const float* __restrict__ W,
    float* __restrict__ C, int M, int Nc, int K)
{
    __shared__ float As[BKt][BM];
    __shared__ float Ws[BKt][BN];

    const int tid = threadIdx.x;
    const int m0 = blockIdx.y * BM;
    const int n0 = blockIdx.x * BN;

    const int ty = tid >> 4;     // 0..15
    const int tx = tid & 15;     // 0..15

    // A tile loaders: row = tid>>1 (0..127), kcol = (tid&1)*4
    const int arow  = tid >> 1;
    const int akcol = (tid & 1) * 4;
    // W tile loaders: krow = tid>>5 (0..7), col = (tid&31)*4
    const int wkrow = tid >> 5;
    const int wcol  = (tid & 31) * 4;

    float acc[TM][TN];
#pragma unroll
    for (int i = 0; i < TM; i++)
#pragma unroll
        for (int j = 0; j < TN; j++) acc[i][j] = 0.f;

    const float* Aptr = A + (size_t)(m0 + arow) * K + akcol;
    const float* Wptr = W + (size_t)wkrow * Nc + n0 + wcol;

    for (int k0 = 0; k0 < K; k0 += BKt) {
        float4 av = *(const float4*)(Aptr + k0);
        float4 wv = *(const float4*)(Wptr + (size_t)k0 * Nc);
        As[akcol + 0][arow] = av.x;
        As[akcol + 1][arow] = av.y;
        As[akcol + 2][arow] = av.z;
        As[akcol + 3][arow] = av.w;
        *(float4*)&Ws[wkrow][wcol] = wv;
        __syncthreads();

#pragma unroll
        for (int kk = 0; kk < BKt; kk++) {
            float a[TM], b[TN];
#pragma unroll
            for (int i = 0; i < TM; i += 4) {
                float4 t = *(const float4*)&As[kk][ty * TM + i];
                a[i] = t.x; a[i+1] = t.y; a[i+2] = t.z; a[i+3] = t.w;
            }
#pragma unroll
            for (int j = 0; j < TN; j += 4) {
                float4 t = *(const float4*)&Ws[kk][tx * TN + j];
                b[j] = t.x; b[j+1] = t.y; b[j+2] = t.z; b[j+3] = t.w;
            }
#pragma unroll
            for (int i = 0; i < TM; i++)
#pragma unroll
                for (int j = 0; j < TN; j++)
                    acc[i][j] += a[i] * b[j];
        }
        __syncthreads();
    }

#pragma unroll
    for (int i = 0; i < TM; i++) {
        float* cp = C + (size_t)(m0 + ty * TM + i) * Nc + n0 + tx * TN;
        *(float4*)cp       = make_float4(acc[i][0], acc[i][1], acc[i][2], acc[i][3]);
        *(float4*)(cp + 4) = make_float4(acc[i][4], acc[i][5], acc[i][6], acc[i][7]);
    }
}

// ---------------------------------------------------------------------------
// Dedicated projection: out[b, n, o] = sum_d x[b,n,d] * Wd[n,d,o], n<16, all b.
// Overwrites rows (b*S + n) of the projection buffer.
// grid = (8 o-tiles, 16 n), 256 threads.
// ---------------------------------------------------------------------------
__global__ __launch_bounds__(256) void ded_proj_kernel(
    const float* __restrict__ x, const float* __restrict__ Wd,
    float* __restrict__ out)
{
    __shared__ float xs[Bb][Dd];     // 32KB
    const int n   = blockIdx.y;
    const int tid = threadIdx.x;

    for (int i = tid; i < Bb * Dd; i += 256) {
        int b = i >> 10, k = i & 1023;
        xs[b][k] = x[((size_t)b * Ss + n) * Dd + k];
    }
    __syncthreads();

    const int o  = blockIdx.x * 128 + (tid & 127);
    const int bg = (tid >> 7) * 4;   // 0 or 4
    const float* W = Wd + (size_t)n * Dd * Dd + o;

    float a0 = 0.f, a1 = 0.f, a2 = 0.f, a3 = 0.f;
#pragma unroll 4
    for (int k = 0; k < Dd; k++) {
        float w = W[(size_t)k * Dd];
        a0 += xs[bg + 0][k] * w;
        a1 += xs[bg + 1][k] * w;
        a2 += xs[bg + 2][k] * w;
        a3 += xs[bg + 3][k] * w;
    }
    out[((size_t)(bg + 0) * Ss + n) * Dd + o] = a0;
    out[((size_t)(bg + 1) * Ss + n) * Dd + o] = a1;
    out[((size_t)(bg + 2) * Ss + n) * Dd + o] = a2;
    out[((size_t)(bg + 3) * Ss + n) * Dd + o] = a3;
}

// ---------------------------------------------------------------------------
// Causal flash attention, fp32. One thread = one q row. grid = (S/128, H, B).
// Q/K/V layout: [b, s, D] with head h at columns h*64..h*64+63.
// ---------------------------------------------------------------------------
#define BQ  128
#define BKT 64

__global__ __launch_bounds__(128) void attn_kernel(
    const float* __restrict__ Q, const float* __restrict__ Kt,
    const float* __restrict__ Vt, float* __restrict__ O)
{
    __shared__ float Ks[BKT][HD];
    __shared__ float Vs[BKT][HD];

    const int b  = blockIdx.z;
    const int h  = blockIdx.y;
    const int q0 = blockIdx.x * BQ;
    const int t  = threadIdx.x;
    const int qi = q0 + t;

    const float* qptr = Q + ((size_t)b * Ss + qi) * Dd + h * HD;
    float q[HD];
#pragma unroll
    for (int d = 0; d < HD; d++) q[d] = qptr[d];

    float o[HD];
#pragma unroll
    for (int d = 0; d < HD; d++) o[d] = 0.f;
    float m = -1e30f, l = 0.f;

    const int kend = q0 + BQ;    // causal: no k beyond the tile's last q
    for (int k0 = 0; k0 < kend; k0 += BKT) {
        for (int i = t; i < BKT * HD; i += 128) {
            int r = i >> 6, c = i & 63;
            size_t g = ((size_t)b * Ss + k0 + r) * Dd + h * HD + c;
            Ks[r][c] = Kt[g];
            Vs[r][c] = Vt[g];
        }
        __syncthreads();

        const int jmax = min(BKT, qi - k0 + 1);
        for (int j = 0; j < jmax; j++) {
            float s = 0.f;
#pragma unroll
            for (int d4 = 0; d4 < HD / 4; d4++) {
                float4 kv = *(const float4*)&Ks[j][d4 * 4];
                s += q[d4*4+0]*kv.x + q[d4*4+1]*kv.y
                   + q[d4*4+2]*kv.z + q[d4*4+3]*kv.w;
            }
            s *= 0.125f;   // 1/sqrt(64)

            if (s > m) {
                float corr = __expf(m - s);
                l *= corr;
#pragma unroll
                for (int d = 0; d < HD; d++) o[d] *= corr;
                m = s;
            }
            float p = __expf(s - m);
            l += p;
#pragma unroll
            for (int d4 = 0; d4 < HD / 4; d4++) {
                float4 vv = *(const float4*)&Vs[j][d4 * 4];
                o[d4*4+0] += p * vv.x; o[d4*4+1] += p * vv.y;
                o[d4*4+2] += p * vv.z; o[d4*4+3] += p * vv.w;
            }
        }
        __syncthreads();
    }

    const float inv = 1.f / l;
    float* optr = O + ((size_t)b * Ss + qi) * Dd + h * HD;
#pragma unroll
    for (int d = 0; d < HD; d++) optr[d] = o[d] * inv;
}

// ---------------------------------------------------------------------------
// Launch
// ---------------------------------------------------------------------------
extern "C" void kernel_launch(void* const* d_in, const int* in_sizes, int n_in,
                              void* d_out, int out_size)
{
    const float* x       = (const float*)d_in[0];
    const float* Wq      = (const float*)d_in[1];
    const float* Wk      = (const float*)d_in[2];
    const float* Wv      = (const float*)d_in[3];
    const float* Wq_ded  = (const float*)d_in[4];
    const float* Wk_ded  = (const float*)d_in[5];
    const float* Wv_ded  = (const float*)d_in[6];
    const float* Wo      = (const float*)d_in[7];

    float* out_o = (float*)d_out;            // [B,S,D]
    float* out_k = out_o + ELEM;             // [B,S,H,HD] == [B,S,D]
    float* out_v = out_k + ELEM;

    float *qbuf = nullptr, *abuf = nullptr;
    cudaGetSymbolAddress((void**)&qbuf, g_q);
    cudaGetSymbolAddress((void**)&abuf, g_attn);

    dim3 gemm_grid(Dd / BN, TOK / BM);       // (8, 64)

    // 1) shared projections (all tokens; first-16 rows fixed up next)
    sgemm_kernel<<<gemm_grid, 256>>>(x, Wq, qbuf,  TOK, Dd, Dd);
    sgemm_kernel<<<gemm_grid, 256>>>(x, Wk, out_k, TOK, Dd, Dd);
    sgemm_kernel<<<gemm_grid, 256>>>(x, Wv, out_v, TOK, Dd, Dd);

    // 2) dedicated-weight rows (token index < 16)
    dim3 ded_grid(Dd / 128, Nn);             // (8, 16)
    ded_proj_kernel<<<ded_grid, 256>>>(x, Wq_ded, qbuf);
    ded_proj_kernel<<<ded_grid, 256>>>(x, Wk_ded, out_k);
    ded_proj_kernel<<<ded_grid, 256>>>(x, Wv_ded, out_v);

    // 3) causal attention
    dim3 attn_grid(Ss / BQ, Hh, Bb);         // (8, 16, 8)
    attn_kernel<<<attn_grid, 128>>>(qbuf, out_k, out_v, abuf);

    // 4) output projection
    sgemm_kernel<<<gemm_grid, 256>>>(abuf, Wo, out_o, TOK, Dd, Dd);
}

// round 2
// speedup vs baseline: 1.7036x; 1.7036x over previous
#include <cuda_runtime.h>
#include <cuda_bf16.h>
#include <math.h>
#include <cstdint>

// Problem constants
#define Bb   8
#define Ss   1024
#define Dd   1024
#define Hh   16
#define HD   64
#define Nn   16
#define TOK  (Bb*Ss)              // 8192
#define ELEM ((size_t)Bb*Ss*Dd)   // 8388608

// Scratch (allocation-free rule: device globals)
__device__ float g_q[ELEM];
__device__ float g_attn[ELEM];
__device__ float g_xt[ELEM];

__device__ __forceinline__ float to_tf32(float x) {
    float y; asm("cvt.rna.tf32.f32 %0, %1;" : "=f"(y) : "f"(x)); return y;
}

// ---------------------------------------------------------------------------
// Elementwise tf32 rounding (x -> xt)
// ---------------------------------------------------------------------------
__global__ __launch_bounds__(256) void round_tf32_kernel(
    const float* __restrict__ in, float* __restrict__ out, int n4)
{
    int i = blockIdx.x * blockDim.x + threadIdx.x;
    int stride = gridDim.x * blockDim.x;
    for (; i < n4; i += stride) {
        float4 v = ((const float4*)in)[i];
        v.x = to_tf32(v.x); v.y = to_tf32(v.y);
        v.z = to_tf32(v.z); v.w = to_tf32(v.w);
        ((float4*)out)[i] = v;
    }
}

// ---------------------------------------------------------------------------
// tf32 tensor-core GEMM: C[M,Nc] = A[M,K] @ W[K,Nc]
// A must be pre-rounded to tf32. W is rounded in the loader.
// 128x128x32 tiles, 256 threads (8 warps, 4m x 2n), mma.m16n8k8 tf32.
// A smem: [m][k] stride 36; W smem: [n][k] stride 36 (transposed at load).
// ---------------------------------------------------------------------------
#define GBM 128
#define GBN 128
#define GBK 32
#define SSTR 36
#define GEMM_SMEM (4*GBM*SSTR*2*2)   // bytes: (As 2 bufs + Ws 2 bufs)

__global__ void __launch_bounds__(256, 2)
tf32_gemm_kernel(const float* __restrict__ A, const float* __restrict__ W,
                 float* __restrict__ C, int M, int Nc, int K)
{
    extern __shared__ float smem[];
    float* As = smem;                    // [2][128*36]
    float* Ws = smem + 2 * GBM * SSTR;   // [2][128*36]

    const int tid  = threadIdx.x;
    const int lane = tid & 31;
    const int wid  = tid >> 5;
    const int wm   = (wid & 3) * 32;     // warp m offset within tile
    const int wn   = (wid >> 2) * 64;    // warp n offset within tile
    const int m0   = blockIdx.y * GBM;
    const int n0   = blockIdx.x * GBN;

    const uint32_t sA = (uint32_t)__cvta_generic_to_shared(As);
    const uint32_t sW = (uint32_t)__cvta_generic_to_shared(Ws);

    float acc[2][8][4];
#pragma unroll
    for (int mf = 0; mf < 2; mf++)
#pragma unroll
        for (int nf = 0; nf < 8; nf++)
#pragma unroll
            for (int r = 0; r < 4; r++) acc[mf][nf][r] = 0.f;

    const float* Abase = A + (size_t)m0 * K;
    const float* Wbase = W + n0;

    // A tile loader: 128 rows x 32 k, 16B cp.async, conflict-free (group = (m+c)%8)
    auto load_a = [&](int k0, int buf) {
        uint32_t dst = sA + (uint32_t)buf * (GBM * SSTR * 4);
#pragma unroll
        for (int j = 0; j < 4; j++) {
            int g = tid + 256 * j;
            int m = g >> 3, c = g & 7;
            const float* src = Abase + (size_t)m * K + k0 + c * 4;
            uint32_t d = dst + (uint32_t)(m * SSTR + c * 4) * 4;
            asm volatile("cp.async.ca.shared.global [%0], [%1], 16;\n"
                         :: "r"(d), "l"(src));
        }
    };

    // W tile loader: global [k][n] -> smem [n][k] (transpose), tf32-rounded.
    // lane = k row (32 rows), wid picks n-chunk; scalar STS are conflict-free
    // (bank = (4n + k) % 32, k distinct across lanes).
    auto load_w = [&](int k0, int buf) {
        float* dstW = Ws + buf * (GBN * SSTR);
        const float* src = Wbase + (size_t)(k0 + lane) * Nc;
        float4 v[4];
#pragma unroll
        for (int j = 0; j < 4; j++)
            v[j] = *(const float4*)(src + (wid + 8 * j) * 4);
#pragma unroll
        for (int j = 0; j < 4; j++) {
            int n = (wid + 8 * j) * 4;
            dstW[(n + 0) * SSTR + lane] = to_tf32(v[j].x);
            dstW[(n + 1) * SSTR + lane] = to_tf32(v[j].y);
            dstW[(n + 2) * SSTR + lane] = to_tf32(v[j].z);
            dstW[(n + 3) * SSTR + lane] = to_tf32(v[j].w);
        }
    };

    auto compute = [&](int buf) {
        const uint32_t baseA = sA + (uint32_t)buf * (GBM * SSTR * 4);
        const uint32_t baseW = sW + (uint32_t)buf * (GBN * SSTR * 4);
        const int q = lane >> 3;     // ldmatrix matrix index for this lane
        const int r = lane & 7;      // row within matrix
#pragma unroll
        for (int k8 = 0; k8 < 4; k8++) {
            uint32_t a[2][4];
#pragma unroll
            for (int mf = 0; mf < 2; mf++) {
                int mrow = wm + mf * 16 + r + (q & 1) * 8;
                int kc   = k8 * 8 + (q >> 1) * 4;
                uint32_t addr = baseA + (uint32_t)(mrow * SSTR + kc) * 4;
                asm volatile(
                    "ldmatrix.sync.aligned.m8n8.x4.shared.b16 {%0,%1,%2,%3}, [%4];"
                    : "=r"(a[mf][0]), "=r"(a[mf][1]), "=r"(a[mf][2]), "=r"(a[mf][3])
                    : "r"(addr));
            }
            uint32_t b[4][4];
#pragma unroll
            for (int p = 0; p < 4; p++) {
                int nrow = wn + (2 * p + (q >> 1)) * 8 + r;
                int kc   = k8 * 8 + (q & 1) * 4;
                uint32_t addr = baseW + (uint32_t)(nrow * SSTR + kc) * 4;
                asm volatile(
                    "ldmatrix.sync.aligned.m8n8.x4.shared.b16 {%0,%1,%2,%3}, [%4];"
                    : "=r"(b[p][0]), "=r"(b[p][1]), "=r"(b[p][2]), "=r"(b[p][3])
                    : "r"(addr));
            }
#pragma unroll
            for (int mf = 0; mf < 2; mf++)
#pragma unroll
                for (int nf = 0; nf < 8; nf++) {
                    uint32_t b0 = b[nf >> 1][(nf & 1) * 2];
                    uint32_t b1 = b[nf >> 1][(nf & 1) * 2 + 1];
                    asm volatile(
                        "mma.sync.aligned.m16n8k8.row.col.f32.tf32.tf32.f32 "
                        "{%0,%1,%2,%3}, {%4,%5,%6,%7}, {%8,%9}, {%0,%1,%2,%3};"
                        : "+f"(acc[mf][nf][0]), "+f"(acc[mf][nf][1]),
                          "+f"(acc[mf][nf][2]), "+f"(acc[mf][nf][3])
                        : "r"(a[mf][0]), "r"(a[mf][1]), "r"(a[mf][2]), "r"(a[mf][3]),
                          "r"(b0), "r"(b1));
                }
        }
    };

    load_a(0, 0);
    asm volatile("cp.async.commit_group;");
    load_w(0, 0);

    int buf = 0;
    for (int k0 = 0; k0 < K; k0 += GBK) {
        asm volatile("cp.async.wait_group 0;");
        __syncthreads();
        if (k0 + GBK < K) {
            load_a(k0 + GBK, buf ^ 1);
            asm volatile("cp.async.commit_group;");
            load_w(k0 + GBK, buf ^ 1);
        }
        compute(buf);
        __syncthreads();
        buf ^= 1;
    }

    // Epilogue
#pragma unroll
    for (int mf = 0; mf < 2; mf++) {
        int row = m0 + wm + mf * 16 + (lane >> 2);
#pragma unroll
        for (int nf = 0; nf < 8; nf++) {
            int col = n0 + wn + nf * 8 + (lane & 3) * 2;
            *(float2*)&C[(size_t)row * Nc + col] =
                make_float2(acc[mf][nf][0], acc[mf][nf][1]);
            *(float2*)&C[(size_t)(row + 8) * Nc + col] =
                make_float2(acc[mf][nf][2], acc[mf][nf][3]);
        }
    }
}

// ---------------------------------------------------------------------------
// Dedicated projection (fused q/k/v): out[b,n,o] = sum_d x[b,n,d]*Wd[n,d,o]
// grid = (16 o-tiles of 64, 16 n, 3 proj), 256 threads. W read exactly once.
// Overwrites rows (b*S + n), n<16 (runs after the shared GEMMs).
// ---------------------------------------------------------------------------
__global__ __launch_bounds__(256) void ded_proj_kernel(
    const float* __restrict__ x,
    const float* __restrict__ Wq_ded, const float* __restrict__ Wk_ded,
    const float* __restrict__ Wv_ded,
    float* __restrict__ qb, float* __restrict__ kb, float* __restrict__ vb)
{
    __shared__ float sm[8192];   // 32KB: xs[8][1024], then partials [16][8][64]
    const int n   = blockIdx.y;
    const int o0  = blockIdx.x * 64;
    const int tid = threadIdx.x;
    const float* Wd = (blockIdx.z == 0) ? Wq_ded : (blockIdx.z == 1 ? Wk_ded : Wv_ded);
    float* out      = (blockIdx.z == 0) ? qb     : (blockIdx.z == 1 ? kb     : vb);

    for (int i = tid; i < Bb * Dd; i += 256) {
        int b = i >> 10, k = i & 1023;
        sm[i] = x[((size_t)b * Ss + n) * Dd + k];
    }
    __syncthreads();

    const int of4 = tid & 15;    // 16 float4 -> 64 o
    const int ks  = tid >> 4;    // 16 k-chunks of 64
    const float* Wp = Wd + (size_t)n * Dd * Dd + (size_t)(ks * 64) * Dd + o0 + of4 * 4;

    float acc[8][4];
#pragma unroll
    for (int b = 0; b < 8; b++)
#pragma unroll
        for (int j = 0; j < 4; j++) acc[b][j] = 0.f;

#pragma unroll 4
    for (int kk = 0; kk < 64; kk++) {
        float4 w = *(const float4*)(Wp + (size_t)kk * Dd);
        int k = ks * 64 + kk;
#pragma unroll
        for (int b = 0; b < 8; b++) {
            float xv = sm[b * 1024 + k];
            acc[b][0] += xv * w.x; acc[b][1] += xv * w.y;
            acc[b][2] += xv * w.z; acc[b][3] += xv * w.w;
        }
    }
    __syncthreads();   // done reading xs; reuse smem for partials

#pragma unroll
    for (int b = 0; b < 8; b++)
        *(float4*)&sm[ks * 512 + b * 64 + of4 * 4] =
            make_float4(acc[b][0], acc[b][1], acc[b][2], acc[b][3]);
    __syncthreads();

    for (int p = tid; p < 512; p += 256) {
        int b = p >> 6, ol = p & 63;
        float s = 0.f;
#pragma unroll
        for (int k2 = 0; k2 < 16; k2++) s += sm[k2 * 512 + p];
        out[((size_t)b * Ss + n) * Dd + o0 + ol] = s;
    }
}

// ---------------------------------------------------------------------------
// Causal flash attention, fp32 SIMT. Output rounded to tf32 (feeds GEMM#4).
// ---------------------------------------------------------------------------
#define BQ  128
#define BKT 64

__global__ __launch_bounds__(128) void attn_kernel(
    const float* __restrict__ Q, const float* __restrict__ Kt,
    const float* __restrict__ Vt, float* __restrict__ O)
{
    __shared__ float Ks[BKT][HD];
    __shared__ float Vs[BKT][HD];

    const int b  = blockIdx.z;
    const int h  = blockIdx.y;
    const int q0 = blockIdx.x * BQ;
    const int t  = threadIdx.x;
    const int qi = q0 + t;

    const float* qptr = Q + ((size_t)b * Ss + qi) * Dd + h * HD;
    float q[HD];
#pragma unroll
    for (int d = 0; d < HD; d++) q[d] = qptr[d];

    float o[HD];
#pragma unroll
    for (int d = 0; d < HD; d++) o[d] = 0.f;
    float m = -1e30f, l = 0.f;

    const int kend = q0 + BQ;
    for (int k0 = 0; k0 < kend; k0 += BKT) {
        for (int i = t; i < BKT * HD; i += 128) {
            int r = i >> 6, c = i & 63;
            size_t g = ((size_t)b * Ss + k0 + r) * Dd + h * HD + c;
            Ks[r][c] = Kt[g];
            Vs[r][c] = Vt[g];
        }
        __syncthreads();

        const int jmax = min(BKT, qi - k0 + 1);
        for (int j = 0; j < jmax; j++) {
            float s = 0.f;
#pragma unroll
            for (int d4 = 0; d4 < HD / 4; d4++) {
                float4 kv = *(const float4*)&Ks[j][d4 * 4];
                s += q[d4*4+0]*kv.x + q[d4*4+1]*kv.y
                   + q[d4*4+2]*kv.z + q[d4*4+3]*kv.w;
            }
            s *= 0.125f;

            if (s > m) {
                float corr = __expf(m - s);
                l *= corr;
#pragma unroll
                for (int d = 0; d < HD; d++) o[d] *= corr;
                m = s;
            }
            float p = __expf(s - m);
            l += p;
#pragma unroll
            for (int d4 = 0; d4 < HD / 4; d4++) {
                float4 vv = *(const float4*)&Vs[j][d4 * 4];
                o[d4*4+0] += p * vv.x; o[d4*4+1] += p * vv.y;
                o[d4*4+2] += p * vv.z; o[d4*4+3] += p * vv.w;
            }
        }
        __syncthreads();
    }

    const float inv = 1.f / l;
    float* optr = O + ((size_t)b * Ss + qi) * Dd + h * HD;
#pragma unroll
    for (int d = 0; d < HD; d++) optr[d] = to_tf32(o[d] * inv);
}

// ---------------------------------------------------------------------------
// Launch
// ---------------------------------------------------------------------------
extern "C" void kernel_launch(void* const* d_in, const int* in_sizes, int n_in,
                              void* d_out, int out_size)
{
    const float* x       = (const float*)d_in[0];
    const float* Wq      = (const float*)d_in[1];
    const float* Wk      = (const float*)d_in[2];
    const float* Wv      = (const float*)d_in[3];
    const float* Wq_ded  = (const float*)d_in[4];
    const float* Wk_ded  = (const float*)d_in[5];
    const float* Wv_ded  = (const float*)d_in[6];
    const float* Wo      = (const float*)d_in[7];

    float* out_o = (float*)d_out;
    float* out_k = out_o + ELEM;
    float* out_v = out_k + ELEM;

    float *qbuf = nullptr, *abuf = nullptr, *xt = nullptr;
    cudaGetSymbolAddress((void**)&qbuf, g_q);
    cudaGetSymbolAddress((void**)&abuf, g_attn);
    cudaGetSymbolAddress((void**)&xt,   g_xt);

    cudaFuncSetAttribute(tf32_gemm_kernel,
                         cudaFuncAttributeMaxDynamicSharedMemorySize, GEMM_SMEM);

    // 0) round x to tf32 once
    round_tf32_kernel<<<2048, 256>>>(x, xt, (int)(ELEM / 4));

    // 1) shared projections on tensor cores
    dim3 gg(Dd / GBN, TOK / GBM);   // (8, 64)
    tf32_gemm_kernel<<<gg, 256, GEMM_SMEM>>>(xt, Wq, qbuf,  TOK, Dd, Dd);
    tf32_gemm_kernel<<<gg, 256, GEMM_SMEM>>>(xt, Wk, out_k, TOK, Dd, Dd);
    tf32_gemm_kernel<<<gg, 256, GEMM_SMEM>>>(xt, Wv, out_v, TOK, Dd, Dd);

    // 2) dedicated-weight rows (fused q/k/v, full fp32)
    dim3 dg(16, Nn, 3);
    ded_proj_kernel<<<dg, 256>>>(x, Wq_ded, Wk_ded, Wv_ded, qbuf, out_k, out_v);

    // 3) causal attention (output tf32-rounded for GEMM#4)
    dim3 ag(Ss / BQ, Hh, Bb);
    attn_kernel<<<ag, 128>>>(qbuf, out_k, out_v, abuf);

    // 4) output projection
    tf32_gemm_kernel<<<gg, 256, GEMM_SMEM>>>(abuf, Wo, out_o, TOK, Dd, Dd);
}

// round 5
// speedup vs baseline: 4.3093x; 2.5296x over previous
#include <cuda_runtime.h>
#include <cuda_bf16.h>
#include <cuda_fp16.h>
#include <math.h>
#include <cstdint>

// Problem constants
#define Bb   8
#define Ss   1024
#define Dd   1024
#define Hh   16
#define HD   64
#define Nn   16
#define TOK  (Bb*Ss)              // 8192
#define ELEM ((size_t)Bb*Ss*Dd)   // 8388608

// Scratch (allocation-free rule: device globals)
__device__ float g_q[ELEM];
__device__ float g_attn[ELEM];
__device__ float g_xt[ELEM];

__device__ __forceinline__ float to_tf32(float x) {
    float y; asm("cvt.rna.tf32.f32 %0, %1;" : "=f"(y) : "f"(x)); return y;
}

__device__ __forceinline__ uint32_t pack_half2(float a, float b) {
    uint32_t r;
    asm("cvt.rn.f16x2.f32 %0, %2, %1;" : "=r"(r) : "f"(a), "f"(b));
    return r;   // low half = a, high half = b
}

// ---------------------------------------------------------------------------
// Elementwise tf32 rounding (x -> xt)
// ---------------------------------------------------------------------------
__global__ __launch_bounds__(256) void round_tf32_kernel(
    const float* __restrict__ in, float* __restrict__ out, int n4)
{
    int i = blockIdx.x * blockDim.x + threadIdx.x;
    int stride = gridDim.x * blockDim.x;
    for (; i < n4; i += stride) {
        float4 v = ((const float4*)in)[i];
        v.x = to_tf32(v.x); v.y = to_tf32(v.y);
        v.z = to_tf32(v.z); v.w = to_tf32(v.w);
        ((float4*)out)[i] = v;
    }
}

// ---------------------------------------------------------------------------
// tf32 tensor-core GEMM: C[M,Nc] = A[M,K] @ W[K,Nc]
// ---------------------------------------------------------------------------
#define GBM 128
#define GBN 128
#define GBK 32
#define SSTR 36
#define GEMM_SMEM (4*GBM*SSTR*2*2)

__global__ void __launch_bounds__(256, 2)
tf32_gemm_kernel(const float* __restrict__ A, const float* __restrict__ W,
                 float* __restrict__ C, int M, int Nc, int K)
{
    extern __shared__ float smem[];
    float* As = smem;
    float* Ws = smem + 2 * GBM * SSTR;

    const int tid  = threadIdx.x;
    const int lane = tid & 31;
    const int wid  = tid >> 5;
    const int wm   = (wid & 3) * 32;
    const int wn   = (wid >> 2) * 64;
    const int m0   = blockIdx.y * GBM;
    const int n0   = blockIdx.x * GBN;

    const uint32_t sA = (uint32_t)__cvta_generic_to_shared(As);
    const uint32_t sW = (uint32_t)__cvta_generic_to_shared(Ws);

    float acc[2][8][4];
#pragma unroll
    for (int mf = 0; mf < 2; mf++)
#pragma unroll
        for (int nf = 0; nf < 8; nf++)
#pragma unroll
            for (int r = 0; r < 4; r++) acc[mf][nf][r] = 0.f;

    const float* Abase = A + (size_t)m0 * K;
    const float* Wbase = W + n0;

    auto load_a = [&](int k0, int buf) {
        uint32_t dst = sA + (uint32_t)buf * (GBM * SSTR * 4);
#pragma unroll
        for (int j = 0; j < 4; j++) {
            int g = tid + 256 * j;
            int m = g >> 3, c = g & 7;
            const float* src = Abase + (size_t)m * K + k0 + c * 4;
            uint32_t d = dst + (uint32_t)(m * SSTR + c * 4) * 4;
            asm volatile("cp.async.ca.shared.global [%0], [%1], 16;\n"
                         :: "r"(d), "l"(src));
        }
    };

    auto load_w = [&](int k0, int buf) {
        float* dstW = Ws + buf * (GBN * SSTR);
        const float* src = Wbase + (size_t)(k0 + lane) * Nc;
        float4 v[4];
#pragma unroll
        for (int j = 0; j < 4; j++)
            v[j] = *(const float4*)(src + (wid + 8 * j) * 4);
#pragma unroll
        for (int j = 0; j < 4; j++) {
            int n = (wid + 8 * j) * 4;
            dstW[(n + 0) * SSTR + lane] = to_tf32(v[j].x);
            dstW[(n + 1) * SSTR + lane] = to_tf32(v[j].y);
            dstW[(n + 2) * SSTR + lane] = to_tf32(v[j].z);
            dstW[(n + 3) * SSTR + lane] = to_tf32(v[j].w);
        }
    };

    auto compute = [&](int buf) {
        const uint32_t baseA = sA + (uint32_t)buf * (GBM * SSTR * 4);
        const uint32_t baseW = sW + (uint32_t)buf * (GBN * SSTR * 4);
        const int q = lane >> 3;
        const int r = lane & 7;
#pragma unroll
        for (int k8 = 0; k8 < 4; k8++) {
            uint32_t a[2][4];
#pragma unroll
            for (int mf = 0; mf < 2; mf++) {
                int mrow = wm + mf * 16 + r + (q & 1) * 8;
                int kc   = k8 * 8 + (q >> 1) * 4;
                uint32_t addr = baseA + (uint32_t)(mrow * SSTR + kc) * 4;
                asm volatile(
                    "ldmatrix.sync.aligned.m8n8.x4.shared.b16 {%0,%1,%2,%3}, [%4];"
                    : "=r"(a[mf][0]), "=r"(a[mf][1]), "=r"(a[mf][2]), "=r"(a[mf][3])
                    : "r"(addr));
            }
            uint32_t b[4][4];
#pragma unroll
            for (int p = 0; p < 4; p++) {
                int nrow = wn + (2 * p + (q >> 1)) * 8 + r;
                int kc   = k8 * 8 + (q & 1) * 4;
                uint32_t addr = baseW + (uint32_t)(nrow * SSTR + kc) * 4;
                asm volatile(
                    "ldmatrix.sync.aligned.m8n8.x4.shared.b16 {%0,%1,%2,%3}, [%4];"
                    : "=r"(b[p][0]), "=r"(b[p][1]), "=r"(b[p][2]), "=r"(b[p][3])
                    : "r"(addr));
            }
#pragma unroll
            for (int mf = 0; mf < 2; mf++)
#pragma unroll
                for (int nf = 0; nf < 8; nf++) {
                    uint32_t b0 = b[nf >> 1][(nf & 1) * 2];
                    uint32_t b1 = b[nf >> 1][(nf & 1) * 2 + 1];
                    asm volatile(
                        "mma.sync.aligned.m16n8k8.row.col.f32.tf32.tf32.f32 "
                        "{%0,%1,%2,%3}, {%4,%5,%6,%7}, {%8,%9}, {%0,%1,%2,%3};"
                        : "+f"(acc[mf][nf][0]), "+f"(acc[mf][nf][1]),
                          "+f"(acc[mf][nf][2]), "+f"(acc[mf][nf][3])
                        : "r"(a[mf][0]), "r"(a[mf][1]), "r"(a[mf][2]), "r"(a[mf][3]),
                          "r"(b0), "r"(b1));
                }
        }
    };

    load_a(0, 0);
    asm volatile("cp.async.commit_group;");
    load_w(0, 0);

    int buf = 0;
    for (int k0 = 0; k0 < K; k0 += GBK) {
        asm volatile("cp.async.wait_group 0;");
        __syncthreads();
        if (k0 + GBK < K) {
            load_a(k0 + GBK, buf ^ 1);
            asm volatile("cp.async.commit_group;");
            load_w(k0 + GBK, buf ^ 1);
        }
        compute(buf);
        __syncthreads();
        buf ^= 1;
    }

#pragma unroll
    for (int mf = 0; mf < 2; mf++) {
        int row = m0 + wm + mf * 16 + (lane >> 2);
#pragma unroll
        for (int nf = 0; nf < 8; nf++) {
            int col = n0 + wn + nf * 8 + (lane & 3) * 2;
            *(float2*)&C[(size_t)row * Nc + col] =
                make_float2(acc[mf][nf][0], acc[mf][nf][1]);
            *(float2*)&C[(size_t)(row + 8) * Nc + col] =
                make_float2(acc[mf][nf][2], acc[mf][nf][3]);
        }
    }
}

// ---------------------------------------------------------------------------
// Dedicated projection (fused q/k/v)
// ---------------------------------------------------------------------------
__global__ __launch_bounds__(256) void ded_proj_kernel(
    const float* __restrict__ x,
    const float* __restrict__ Wq_ded, const float* __restrict__ Wk_ded,
    const float* __restrict__ Wv_ded,
    float* __restrict__ qb, float* __restrict__ kb, float* __restrict__ vb)
{
    __shared__ float sm[8192];
    const int n   = blockIdx.y;
    const int o0  = blockIdx.x * 64;
    const int tid = threadIdx.x;
    const float* Wd = (blockIdx.z == 0) ? Wq_ded : (blockIdx.z == 1 ? Wk_ded : Wv_ded);
    float* out      = (blockIdx.z == 0) ? qb     : (blockIdx.z == 1 ? kb     : vb);

    for (int i = tid; i < Bb * Dd; i += 256) {
        int b = i >> 10, k = i & 1023;
        sm[i] = x[((size_t)b * Ss + n) * Dd + k];
    }
    __syncthreads();

    const int of4 = tid & 15;
    const int ks  = tid >> 4;
    const float* Wp = Wd + (size_t)n * Dd * Dd + (size_t)(ks * 64) * Dd + o0 + of4 * 4;

    float acc[8][4];
#pragma unroll
    for (int b = 0; b < 8; b++)
#pragma unroll
        for (int j = 0; j < 4; j++) acc[b][j] = 0.f;

#pragma unroll 4
    for (int kk = 0; kk < 64; kk++) {
        float4 w = *(const float4*)(Wp + (size_t)kk * Dd);
        int k = ks * 64 + kk;
#pragma unroll
        for (int b = 0; b < 8; b++) {
            float xv = sm[b * 1024 + k];
            acc[b][0] += xv * w.x; acc[b][1] += xv * w.y;
            acc[b][2] += xv * w.z; acc[b][3] += xv * w.w;
        }
    }
    __syncthreads();

#pragma unroll
    for (int b = 0; b < 8; b++)
        *(float4*)&sm[ks * 512 + b * 64 + of4 * 4] =
            make_float4(acc[b][0], acc[b][1], acc[b][2], acc[b][3]);
    __syncthreads();

    for (int p = tid; p < 512; p += 256) {
        int b = p >> 6, ol = p & 63;
        float s = 0.f;
#pragma unroll
        for (int k2 = 0; k2 < 16; k2++) s += sm[k2 * 512 + p];
        out[((size_t)b * Ss + n) * Dd + o0 + ol] = s;
    }
}

// ---------------------------------------------------------------------------
// Tensor-core causal flash attention.
// Block: 256 thr (8 warps x 16 q-rows = 128 q-rows). KV tiles of 64.
// S = Q@K^T via mma.m16n8k8.tf32 ; P@V via mma.m16n8k16.f16 (V fp16 in smem).
// K smem rows are HD=64 floats -> KSTR = 68 (64 + 4 pad). Dynamic smem.
// ---------------------------------------------------------------------------
#define ABQ 128
#define ABK 64
#define KSTR 68   // floats per K smem row (64 data + 4 pad)
#define VSTR 72   // halfs per V smem row  (64 data + 8 pad)
#define ATTN_SMEM (2*ABK*KSTR*4 + 2*ABK*VSTR*2)   // 53248 bytes

__global__ __launch_bounds__(256) void attn_tc_kernel(
    const float* __restrict__ Q, const float* __restrict__ Kt,
    const float* __restrict__ Vt, float* __restrict__ O)
{
    extern __shared__ char asmem[];
    float*  Ks = (float*)asmem;                          // [2][ABK*KSTR]
    __half* Vs = (__half*)(asmem + 2 * ABK * KSTR * 4);  // [2][ABK*VSTR]

    const int b   = blockIdx.z;
    const int h   = blockIdx.y;
    const int q0  = blockIdx.x * ABQ;
    const int tid = threadIdx.x;
    const int lane = tid & 31;
    const int wid  = tid >> 5;
    const int wq0  = q0 + wid * 16;
    const int r = lane >> 2;      // quad row
    const int c = lane & 3;       // quad col

    const uint32_t sKs = (uint32_t)__cvta_generic_to_shared(Ks);
    const uint32_t sVs = (uint32_t)__cvta_generic_to_shared(Vs);

    // Q fragments (canonical m16n8k8 tf32 A layout); HW truncates to tf32.
    float qf[8][4];
    {
        const float* q0p = Q + ((size_t)(b * Ss) + wq0 + r) * Dd + h * HD;
        const float* q1p = q0p + 8 * (size_t)Dd;
#pragma unroll
        for (int k8 = 0; k8 < 8; k8++) {
            qf[k8][0] = q0p[k8 * 8 + c];
            qf[k8][1] = q1p[k8 * 8 + c];
            qf[k8][2] = q0p[k8 * 8 + c + 4];
            qf[k8][3] = q1p[k8 * 8 + c + 4];
        }
    }

    const float* Kbase = Kt + (size_t)(b * Ss) * Dd + h * HD;
    const float* Vbase = Vt + (size_t)(b * Ss) * Dd + h * HD;

    auto load_k = [&](int k0, int buf) {
        uint32_t dst = sKs + (uint32_t)buf * (ABK * KSTR * 4);
#pragma unroll
        for (int j = 0; j < 4; j++) {
            int g = tid + 256 * j;
            int row = g >> 4, c4 = g & 15;
            const float* src = Kbase + (size_t)(k0 + row) * Dd + c4 * 4;
            asm volatile("cp.async.ca.shared.global [%0], [%1], 16;\n"
                         :: "r"(dst + (uint32_t)(row * KSTR + c4 * 4) * 4), "l"(src));
        }
    };
    auto load_v = [&](int k0, int buf) {
        __half* dstV = Vs + buf * (ABK * VSTR);
#pragma unroll
        for (int j = 0; j < 4; j++) {
            int g = tid + 256 * j;
            int row = g >> 4, c4 = g & 15;
            float4 v = *(const float4*)(Vbase + (size_t)(k0 + row) * Dd + c4 * 4);
            __half2 h0 = __floats2half2_rn(v.x, v.y);
            __half2 h1 = __floats2half2_rn(v.z, v.w);
            *(__half2*)&dstV[row * VSTR + c4 * 4]     = h0;
            *(__half2*)&dstV[row * VSTR + c4 * 4 + 2] = h1;
        }
    };

    float o[8][4];
#pragma unroll
    for (int j = 0; j < 8; j++)
#pragma unroll
        for (int e = 0; e < 4; e++) o[j][e] = 0.f;
    float m0 = -1e30f, m1 = -1e30f, l0 = 0.f, l1 = 0.f;

    const int kend = q0 + ABQ;
    load_k(0, 0);
    asm volatile("cp.async.commit_group;");
    load_v(0, 0);

    int buf = 0;
    const int ql = lane >> 3, rl = lane & 7;

    for (int k0 = 0; k0 < kend; k0 += ABK) {
        asm volatile("cp.async.wait_group 0;");
        __syncthreads();
        if (k0 + ABK < kend) {
            load_k(k0 + ABK, buf ^ 1);
            asm volatile("cp.async.commit_group;");
            load_v(k0 + ABK, buf ^ 1);
        }

        if (k0 <= wq0 + 15) {   // warp has at least one unmasked row in tile
            // ---- S = Q @ K^T (tf32) ----
            float s[8][4];
#pragma unroll
            for (int j = 0; j < 8; j++)
#pragma unroll
                for (int e = 0; e < 4; e++) s[j][e] = 0.f;

            const uint32_t baseK = sKs + (uint32_t)buf * (ABK * KSTR * 4);
#pragma unroll
            for (int k8 = 0; k8 < 8; k8++) {
                uint32_t bk[4][4];
#pragma unroll
                for (int p = 0; p < 4; p++) {
                    int nrow = (2 * p + (ql >> 1)) * 8 + rl;
                    int kc   = k8 * 8 + (ql & 1) * 4;
                    uint32_t addr = baseK + (uint32_t)(nrow * KSTR + kc) * 4;
                    asm volatile(
                        "ldmatrix.sync.aligned.m8n8.x4.shared.b16 {%0,%1,%2,%3}, [%4];"
                        : "=r"(bk[p][0]), "=r"(bk[p][1]), "=r"(bk[p][2]), "=r"(bk[p][3])
                        : "r"(addr));
                }
#pragma unroll
                for (int j = 0; j < 8; j++) {
                    uint32_t b0 = bk[j >> 1][(j & 1) * 2];
                    uint32_t b1 = bk[j >> 1][(j & 1) * 2 + 1];
                    asm volatile(
                        "mma.sync.aligned.m16n8k8.row.col.f32.tf32.tf32.f32 "
                        "{%0,%1,%2,%3}, {%4,%5,%6,%7}, {%8,%9}, {%0,%1,%2,%3};"
                        : "+f"(s[j][0]), "+f"(s[j][1]), "+f"(s[j][2]), "+f"(s[j][3])
                        : "r"(__float_as_uint(qf[k8][0])), "r"(__float_as_uint(qf[k8][1])),
                          "r"(__float_as_uint(qf[k8][2])), "r"(__float_as_uint(qf[k8][3])),
                          "r"(b0), "r"(b1));
                }
            }

            // ---- scale + causal mask + online softmax ----
            const bool need_mask = (k0 + 63 > wq0);
            float rmax0 = -1e30f, rmax1 = -1e30f;
#pragma unroll
            for (int j = 0; j < 8; j++) {
#pragma unroll
                for (int e = 0; e < 2; e++) {
                    float v0 = s[j][e]     * 0.125f;
                    float v1 = s[j][2 + e] * 0.125f;
                    if (need_mask) {
                        int col = k0 + j * 8 + 2 * c + e;
                        if (col > wq0 + r)     v0 = -1e30f;
                        if (col > wq0 + r + 8) v1 = -1e30f;
                    }
                    s[j][e] = v0; s[j][2 + e] = v1;
                    rmax0 = fmaxf(rmax0, v0);
                    rmax1 = fmaxf(rmax1, v1);
                }
            }
            rmax0 = fmaxf(rmax0, __shfl_xor_sync(0xffffffffu, rmax0, 1));
            rmax0 = fmaxf(rmax0, __shfl_xor_sync(0xffffffffu, rmax0, 2));
            rmax1 = fmaxf(rmax1, __shfl_xor_sync(0xffffffffu, rmax1, 1));
            rmax1 = fmaxf(rmax1, __shfl_xor_sync(0xffffffffu, rmax1, 2));

            float mn0 = fmaxf(m0, rmax0), mn1 = fmaxf(m1, rmax1);
            float corr0 = __expf(m0 - mn0), corr1 = __expf(m1 - mn1);
            m0 = mn0; m1 = mn1;

            float ls0 = 0.f, ls1 = 0.f;
#pragma unroll
            for (int j = 0; j < 8; j++) {
                s[j][0] = __expf(s[j][0] - mn0);
                s[j][1] = __expf(s[j][1] - mn0);
                s[j][2] = __expf(s[j][2] - mn1);
                s[j][3] = __expf(s[j][3] - mn1);
                ls0 += s[j][0] + s[j][1];
                ls1 += s[j][2] + s[j][3];
            }
            l0 = l0 * corr0 + ls0;
            l1 = l1 * corr1 + ls1;
#pragma unroll
            for (int j = 0; j < 8; j++) {
                o[j][0] *= corr0; o[j][1] *= corr0;
                o[j][2] *= corr1; o[j][3] *= corr1;
            }

            // ---- O += P @ V (fp16) ----
#pragma unroll
            for (int kk = 0; kk < 4; kk++) {
                uint32_t a0 = pack_half2(s[2*kk][0],   s[2*kk][1]);
                uint32_t a1 = pack_half2(s[2*kk][2],   s[2*kk][3]);
                uint32_t a2 = pack_half2(s[2*kk+1][0], s[2*kk+1][1]);
                uint32_t a3 = pack_half2(s[2*kk+1][2], s[2*kk+1][3]);
#pragma unroll
                for (int jj = 0; jj < 4; jj++) {
                    uint32_t addr = sVs + (uint32_t)buf * (ABK * VSTR * 2)
                        + (uint32_t)((kk * 16 + (lane & 15)) * VSTR
                                     + jj * 16 + (lane >> 4) * 8) * 2;
                    uint32_t v0, v1, v2, v3;
                    asm volatile(
                        "ldmatrix.sync.aligned.m8n8.x4.trans.shared.b16 {%0,%1,%2,%3}, [%4];"
                        : "=r"(v0), "=r"(v1), "=r"(v2), "=r"(v3) : "r"(addr));
                    asm volatile(
                        "mma.sync.aligned.m16n8k16.row.col.f32.f16.f16.f32 "
                        "{%0,%1,%2,%3}, {%4,%5,%6,%7}, {%8,%9}, {%0,%1,%2,%3};"
                        : "+f"(o[2*jj][0]), "+f"(o[2*jj][1]), "+f"(o[2*jj][2]), "+f"(o[2*jj][3])
                        : "r"(a0), "r"(a1), "r"(a2), "r"(a3), "r"(v0), "r"(v1));
                    asm volatile(
                        "mma.sync.aligned.m16n8k16.row.col.f32.f16.f16.f32 "
                        "{%0,%1,%2,%3}, {%4,%5,%6,%7}, {%8,%9}, {%0,%1,%2,%3};"
                        : "+f"(o[2*jj+1][0]), "+f"(o[2*jj+1][1]), "+f"(o[2*jj+1][2]), "+f"(o[2*jj+1][3])
                        : "r"(a0), "r"(a1), "r"(a2), "r"(a3), "r"(v2), "r"(v3));
                }
            }
        }
        __syncthreads();
        buf ^= 1;
    }

    // final row-sum reduction across the quad
    l0 += __shfl_xor_sync(0xffffffffu, l0, 1);
    l0 += __shfl_xor_sync(0xffffffffu, l0, 2);
    l1 += __shfl_xor_sync(0xffffffffu, l1, 1);
    l1 += __shfl_xor_sync(0xffffffffu, l1, 2);
    const float inv0 = 1.f / l0, inv1 = 1.f / l1;

    float* o0p = O + ((size_t)(b * Ss) + wq0 + r) * Dd + h * HD;
    float* o1p = o0p + 8 * (size_t)Dd;
#pragma unroll
    for (int j = 0; j < 8; j++) {
        int col = j * 8 + 2 * c;
        *(float2*)&o0p[col] = make_float2(to_tf32(o[j][0] * inv0),
                                          to_tf32(o[j][1] * inv0));
        *(float2*)&o1p[col] = make_float2(to_tf32(o[j][2] * inv1),
                                          to_tf32(o[j][3] * inv1));
    }
}

// ---------------------------------------------------------------------------
// Launch
// ---------------------------------------------------------------------------
extern "C" void kernel_launch(void* const* d_in, const int* in_sizes, int n_in,
                              void* d_out, int out_size)
{
    const float* x       = (const float*)d_in[0];
    const float* Wq      = (const float*)d_in[1];
    const float* Wk      = (const float*)d_in[2];
    const float* Wv      = (const float*)d_in[3];
    const float* Wq_ded  = (const float*)d_in[4];
    const float* Wk_ded  = (const float*)d_in[5];
    const float* Wv_ded  = (const float*)d_in[6];
    const float* Wo      = (const float*)d_in[7];

    float* out_o = (float*)d_out;
    float* out_k = out_o + ELEM;
    float* out_v = out_k + ELEM;

    float *qbuf = nullptr, *abuf = nullptr, *xt = nullptr;
    cudaGetSymbolAddress((void**)&qbuf, g_q);
    cudaGetSymbolAddress((void**)&abuf, g_attn);
    cudaGetSymbolAddress((void**)&xt,   g_xt);

    cudaFuncSetAttribute(tf32_gemm_kernel,
                         cudaFuncAttributeMaxDynamicSharedMemorySize, GEMM_SMEM);
    cudaFuncSetAttribute(attn_tc_kernel,
                         cudaFuncAttributeMaxDynamicSharedMemorySize, ATTN_SMEM);

    // 0) round x to tf32 once
    round_tf32_kernel<<<2048, 256>>>(x, xt, (int)(ELEM / 4));

    // 1) shared projections on tensor cores
    dim3 gg(Dd / GBN, TOK / GBM);
    tf32_gemm_kernel<<<gg, 256, GEMM_SMEM>>>(xt, Wq, qbuf,  TOK, Dd, Dd);
    tf32_gemm_kernel<<<gg, 256, GEMM_SMEM>>>(xt, Wk, out_k, TOK, Dd, Dd);
    tf32_gemm_kernel<<<gg, 256, GEMM_SMEM>>>(xt, Wv, out_v, TOK, Dd, Dd);

    // 2) dedicated-weight rows
    dim3 dg(16, Nn, 3);
    ded_proj_kernel<<<dg, 256>>>(x, Wq_ded, Wk_ded, Wv_ded, qbuf, out_k, out_v);

    // 3) tensor-core causal attention (output tf32-rounded for GEMM#4)
    dim3 ag(Ss / ABQ, Hh, Bb);
    attn_tc_kernel<<<ag, 256, ATTN_SMEM>>>(qbuf, out_k, out_v, abuf);

    // 4) output projection
    tf32_gemm_kernel<<<gg, 256, GEMM_SMEM>>>(abuf, Wo, out_o, TOK, Dd, Dd);
}

// round 7
// speedup vs baseline: 5.9107x; 1.3716x over previous
#include <cuda_runtime.h>
#include <cuda_bf16.h>
#include <cuda_fp16.h>
#include <math.h>
#include <cstdint>

// Problem constants
#define Bb   8
#define Ss   1024
#define Dd   1024
#define Hh   16
#define HD   64
#define Nn   16
#define TOK  (Bb*Ss)              // 8192
#define ELEM ((size_t)Bb*Ss*Dd)   // 8388608

// Scratch (allocation-free rule: device globals)
__device__ float g_q[ELEM];
__device__ float g_attn[ELEM];
__device__ float g_xt[ELEM];
__device__ float g_wt[4][Dd * Dd];   // transposed+rounded Wq,Wk,Wv,Wo

__device__ __forceinline__ float to_tf32(float x) {
    float y; asm("cvt.rna.tf32.f32 %0, %1;" : "=f"(y) : "f"(x)); return y;
}

__device__ __forceinline__ uint32_t pack_half2(float a, float b) {
    uint32_t r;
    asm("cvt.rn.f16x2.f32 %0, %2, %1;" : "=r"(r) : "f"(a), "f"(b));
    return r;
}

// ---------------------------------------------------------------------------
// Elementwise tf32 rounding (x -> xt)
// ---------------------------------------------------------------------------
__global__ __launch_bounds__(256) void round_tf32_kernel(
    const float* __restrict__ in, float* __restrict__ out, int n4)
{
    int i = blockIdx.x * blockDim.x + threadIdx.x;
    int stride = gridDim.x * blockDim.x;
    for (; i < n4; i += stride) {
        float4 v = ((const float4*)in)[i];
        v.x = to_tf32(v.x); v.y = to_tf32(v.y);
        v.z = to_tf32(v.z); v.w = to_tf32(v.w);
        ((float4*)out)[i] = v;
    }
}

// ---------------------------------------------------------------------------
// W transpose + tf32 round: out[n][k] = tf32(in[k][n]), 1024x1024
// ---------------------------------------------------------------------------
__global__ __launch_bounds__(256) void transpose_tf32_kernel(
    const float* __restrict__ in, float* __restrict__ out)
{
    __shared__ float t[32][33];
    int x = blockIdx.x * 32 + threadIdx.x;
    int y = blockIdx.y * 32 + threadIdx.y;
#pragma unroll
    for (int j = 0; j < 32; j += 8)
        t[threadIdx.y + j][threadIdx.x] = to_tf32(in[(size_t)(y + j) * Dd + x]);
    __syncthreads();
    x = blockIdx.y * 32 + threadIdx.x;
    y = blockIdx.x * 32 + threadIdx.y;
#pragma unroll
    for (int j = 0; j < 32; j += 8)
        out[(size_t)(y + j) * Dd + x] = t[threadIdx.x][threadIdx.y + j];
}

// ---------------------------------------------------------------------------
// tf32 tensor-core GEMM v2: C[M,Nc] = A[M,K] @ Wt[Nc,K]^T
// Both operands pre-rounded to tf32; Wt is [n][k] (pre-transposed).
// CTA tile 128x256, GBK=32, 256 threads, warps 2m x 4n (64x64 each),
// 3-stage cp.async pipeline. All smem fills are 16B cp.async.
// ---------------------------------------------------------------------------
#define GBM 128
#define GBN 256
#define GBK 32
#define SSTR 36
#define NSTAGE 3
#define GEMM_SMEM ((NSTAGE*GBM*SSTR + NSTAGE*GBN*SSTR) * 4)   // 165888 B

__global__ void __launch_bounds__(256, 1)
tf32_gemm_kernel(const float* __restrict__ A,
                 const float* __restrict__ Wt0, const float* __restrict__ Wt1,
                 const float* __restrict__ Wt2,
                 float* __restrict__ C0, float* __restrict__ C1,
                 float* __restrict__ C2, int K)
{
    extern __shared__ float smem[];
    float* As = smem;                          // [NSTAGE][GBM*SSTR]
    float* Bs = smem + NSTAGE * GBM * SSTR;    // [NSTAGE][GBN*SSTR]

    const float* Wt = (blockIdx.z == 0) ? Wt0 : (blockIdx.z == 1 ? Wt1 : Wt2);
    float* C        = (blockIdx.z == 0) ? C0  : (blockIdx.z == 1 ? C1  : C2);

    const int tid  = threadIdx.x;
    const int lane = tid & 31;
    const int wid  = tid >> 5;
    const int wm   = (wid & 1) * 64;     // 2 warps in m
    const int wn   = (wid >> 1) * 64;    // 4 warps in n
    const int m0   = blockIdx.y * GBM;
    const int n0   = blockIdx.x * GBN;

    const uint32_t sA = (uint32_t)__cvta_generic_to_shared(As);
    const uint32_t sB = (uint32_t)__cvta_generic_to_shared(Bs);

    float acc[4][8][4];
#pragma unroll
    for (int mf = 0; mf < 4; mf++)
#pragma unroll
        for (int nf = 0; nf < 8; nf++)
#pragma unroll
            for (int r = 0; r < 4; r++) acc[mf][nf][r] = 0.f;

    const float* Abase = A + (size_t)m0 * K;
    const float* Bbase = Wt + (size_t)n0 * K;

    auto load_tile = [&](int k0, int st) {
        uint32_t dstA = sA + (uint32_t)st * (GBM * SSTR * 4);
#pragma unroll
        for (int j = 0; j < 4; j++) {
            int g = tid + 256 * j;
            int m = g >> 3, c = g & 7;
            const float* src = Abase + (size_t)m * K + k0 + c * 4;
            asm volatile("cp.async.ca.shared.global [%0], [%1], 16;\n"
                         :: "r"(dstA + (uint32_t)(m * SSTR + c * 4) * 4), "l"(src));
        }
        uint32_t dstB = sB + (uint32_t)st * (GBN * SSTR * 4);
#pragma unroll
        for (int j = 0; j < 8; j++) {
            int g = tid + 256 * j;
            int n = g >> 3, c = g & 7;
            const float* src = Bbase + (size_t)n * K + k0 + c * 4;
            asm volatile("cp.async.ca.shared.global [%0], [%1], 16;\n"
                         :: "r"(dstB + (uint32_t)(n * SSTR + c * 4) * 4), "l"(src));
        }
    };

    const int ql = lane >> 3, rl = lane & 7;

    auto compute = [&](int st) {
        const uint32_t baseA = sA + (uint32_t)st * (GBM * SSTR * 4);
        const uint32_t baseB = sB + (uint32_t)st * (GBN * SSTR * 4);
#pragma unroll
        for (int k8 = 0; k8 < 4; k8++) {
            uint32_t a[4][4];
#pragma unroll
            for (int mf = 0; mf < 4; mf++) {
                int mrow = wm + mf * 16 + rl + (ql & 1) * 8;
                int kc   = k8 * 8 + (ql >> 1) * 4;
                uint32_t addr = baseA + (uint32_t)(mrow * SSTR + kc) * 4;
                asm volatile(
                    "ldmatrix.sync.aligned.m8n8.x4.shared.b16 {%0,%1,%2,%3}, [%4];"
                    : "=r"(a[mf][0]), "=r"(a[mf][1]), "=r"(a[mf][2]), "=r"(a[mf][3])
                    : "r"(addr));
            }
            uint32_t b[4][4];
#pragma unroll
            for (int p = 0; p < 4; p++) {
                int nrow = wn + (2 * p + (ql >> 1)) * 8 + rl;
                int kc   = k8 * 8 + (ql & 1) * 4;
                uint32_t addr = baseB + (uint32_t)(nrow * SSTR + kc) * 4;
                asm volatile(
                    "ldmatrix.sync.aligned.m8n8.x4.shared.b16 {%0,%1,%2,%3}, [%4];"
                    : "=r"(b[p][0]), "=r"(b[p][1]), "=r"(b[p][2]), "=r"(b[p][3])
                    : "r"(addr));
            }
#pragma unroll
            for (int mf = 0; mf < 4; mf++)
#pragma unroll
                for (int nf = 0; nf < 8; nf++) {
                    uint32_t b0 = b[nf >> 1][(nf & 1) * 2];
                    uint32_t b1 = b[nf >> 1][(nf & 1) * 2 + 1];
                    asm volatile(
                        "mma.sync.aligned.m16n8k8.row.col.f32.tf32.tf32.f32 "
                        "{%0,%1,%2,%3}, {%4,%5,%6,%7}, {%8,%9}, {%0,%1,%2,%3};"
                        : "+f"(acc[mf][nf][0]), "+f"(acc[mf][nf][1]),
                          "+f"(acc[mf][nf][2]), "+f"(acc[mf][nf][3])
                        : "r"(a[mf][0]), "r"(a[mf][1]), "r"(a[mf][2]), "r"(a[mf][3]),
                          "r"(b0), "r"(b1));
                }
        }
    };

    // Prologue: stages 0,1 hold k-tiles 0,1
    load_tile(0, 0);
    asm volatile("cp.async.commit_group;");
    load_tile(GBK, 1);
    asm volatile("cp.async.commit_group;");

    // Iteration i: group i (tile i) is guaranteed complete by wait_group 1,
    // because exactly one group is committed per iteration (empty at tail).
    // Prefetch goes to stage (i+2)%3 — consumed at iter i-1, protected by
    // the top-of-loop __syncthreads().
    const int niter = K / GBK;
    for (int i = 0; i < niter; i++) {
        asm volatile("cp.async.wait_group 1;");
        __syncthreads();
        if ((i + 2) * GBK < K)
            load_tile((i + 2) * GBK, (i + 2) % NSTAGE);
        asm volatile("cp.async.commit_group;");
        compute(i % NSTAGE);
    }

    // Epilogue
#pragma unroll
    for (int mf = 0; mf < 4; mf++) {
        int row = m0 + wm + mf * 16 + (lane >> 2);
#pragma unroll
        for (int nf = 0; nf < 8; nf++) {
            int col = n0 + wn + nf * 8 + (lane & 3) * 2;
            *(float2*)&C[(size_t)row * Dd + col] =
                make_float2(acc[mf][nf][0], acc[mf][nf][1]);
            *(float2*)&C[(size_t)(row + 8) * Dd + col] =
                make_float2(acc[mf][nf][2], acc[mf][nf][3]);
        }
    }
}

// ---------------------------------------------------------------------------
// Dedicated projection (fused q/k/v)
// ---------------------------------------------------------------------------
__global__ __launch_bounds__(256) void ded_proj_kernel(
    const float* __restrict__ x,
    const float* __restrict__ Wq_ded, const float* __restrict__ Wk_ded,
    const float* __restrict__ Wv_ded,
    float* __restrict__ qb, float* __restrict__ kb, float* __restrict__ vb)
{
    __shared__ float sm[8192];
    const int n   = blockIdx.y;
    const int o0  = blockIdx.x * 64;
    const int tid = threadIdx.x;
    const float* Wd = (blockIdx.z == 0) ? Wq_ded : (blockIdx.z == 1 ? Wk_ded : Wv_ded);
    float* out      = (blockIdx.z == 0) ? qb     : (blockIdx.z == 1 ? kb     : vb);

    for (int i = tid; i < Bb * Dd; i += 256) {
        int b = i >> 10, k = i & 1023;
        sm[i] = x[((size_t)b * Ss + n) * Dd + k];
    }
    __syncthreads();

    const int of4 = tid & 15;
    const int ks  = tid >> 4;
    const float* Wp = Wd + (size_t)n * Dd * Dd + (size_t)(ks * 64) * Dd + o0 + of4 * 4;

    float acc[8][4];
#pragma unroll
    for (int b = 0; b < 8; b++)
#pragma unroll
        for (int j = 0; j < 4; j++) acc[b][j] = 0.f;

#pragma unroll 4
    for (int kk = 0; kk < 64; kk++) {
        float4 w = *(const float4*)(Wp + (size_t)kk * Dd);
        int k = ks * 64 + kk;
#pragma unroll
        for (int b = 0; b < 8; b++) {
            float xv = sm[b * 1024 + k];
            acc[b][0] += xv * w.x; acc[b][1] += xv * w.y;
            acc[b][2] += xv * w.z; acc[b][3] += xv * w.w;
        }
    }
    __syncthreads();

#pragma unroll
    for (int b = 0; b < 8; b++)
        *(float4*)&sm[ks * 512 + b * 64 + of4 * 4] =
            make_float4(acc[b][0], acc[b][1], acc[b][2], acc[b][3]);
    __syncthreads();

    for (int p = tid; p < 512; p += 256) {
        int b = p >> 6, ol = p & 63;
        float s = 0.f;
#pragma unroll
        for (int k2 = 0; k2 < 16; k2++) s += sm[k2 * 512 + p];
        out[((size_t)b * Ss + n) * Dd + o0 + ol] = s;
    }
}

// ---------------------------------------------------------------------------
// Tensor-core causal flash attention (unchanged from R5 pass).
// ---------------------------------------------------------------------------
#define ABQ 128
#define ABK 64
#define KSTR 68
#define VSTR 72
#define ATTN_SMEM (2*ABK*KSTR*4 + 2*ABK*VSTR*2)

__global__ __launch_bounds__(256) void attn_tc_kernel(
    const float* __restrict__ Q, const float* __restrict__ Kt,
    const float* __restrict__ Vt, float* __restrict__ O)
{
    extern __shared__ char asmem[];
    float*  Ks = (float*)asmem;
    __half* Vs = (__half*)(asmem + 2 * ABK * KSTR * 4);

    const int b   = blockIdx.z;
    const int h   = blockIdx.y;
    const int q0  = blockIdx.x * ABQ;
    const int tid = threadIdx.x;
    const int lane = tid & 31;
    const int wid  = tid >> 5;
    const int wq0  = q0 + wid * 16;
    const int r = lane >> 2;
    const int c = lane & 3;

    const uint32_t sKs = (uint32_t)__cvta_generic_to_shared(Ks);
    const uint32_t sVs = (uint32_t)__cvta_generic_to_shared(Vs);

    float qf[8][4];
    {
        const float* q0p = Q + ((size_t)(b * Ss) + wq0 + r) * Dd + h * HD;
        const float* q1p = q0p + 8 * (size_t)Dd;
#pragma unroll
        for (int k8 = 0; k8 < 8; k8++) {
            qf[k8][0] = q0p[k8 * 8 + c];
            qf[k8][1] = q1p[k8 * 8 + c];
            qf[k8][2] = q0p[k8 * 8 + c + 4];
            qf[k8][3] = q1p[k8 * 8 + c + 4];
        }
    }

    const float* Kbase = Kt + (size_t)(b * Ss) * Dd + h * HD;
    const float* Vbase = Vt + (size_t)(b * Ss) * Dd + h * HD;

    auto load_k = [&](int k0, int buf) {
        uint32_t dst = sKs + (uint32_t)buf * (ABK * KSTR * 4);
#pragma unroll
        for (int j = 0; j < 4; j++) {
            int g = tid + 256 * j;
            int row = g >> 4, c4 = g & 15;
            const float* src = Kbase + (size_t)(k0 + row) * Dd + c4 * 4;
            asm volatile("cp.async.ca.shared.global [%0], [%1], 16;\n"
                         :: "r"(dst + (uint32_t)(row * KSTR + c4 * 4) * 4), "l"(src));
        }
    };
    auto load_v = [&](int k0, int buf) {
        __half* dstV = Vs + buf * (ABK * VSTR);
#pragma unroll
        for (int j = 0; j < 4; j++) {
            int g = tid + 256 * j;
            int row = g >> 4, c4 = g & 15;
            float4 v = *(const float4*)(Vbase + (size_t)(k0 + row) * Dd + c4 * 4);
            __half2 h0 = __floats2half2_rn(v.x, v.y);
            __half2 h1 = __floats2half2_rn(v.z, v.w);
            *(__half2*)&dstV[row * VSTR + c4 * 4]     = h0;
            *(__half2*)&dstV[row * VSTR + c4 * 4 + 2] = h1;
        }
    };

    float o[8][4];
#pragma unroll
    for (int j = 0; j < 8; j++)
#pragma unroll
        for (int e = 0; e < 4; e++) o[j][e] = 0.f;
    float m0 = -1e30f, m1 = -1e30f, l0 = 0.f, l1 = 0.f;

    const int kend = q0 + ABQ;
    load_k(0, 0);
    asm volatile("cp.async.commit_group;");
    load_v(0, 0);

    int buf = 0;
    const int ql = lane >> 3, rl = lane & 7;

    for (int k0 = 0; k0 < kend; k0 += ABK) {
        asm volatile("cp.async.wait_group 0;");
        __syncthreads();
        if (k0 + ABK < kend) {
            load_k(k0 + ABK, buf ^ 1);
            asm volatile("cp.async.commit_group;");
            load_v(k0 + ABK, buf ^ 1);
        }

        if (k0 <= wq0 + 15) {
            float s[8][4];
#pragma unroll
            for (int j = 0; j < 8; j++)
#pragma unroll
                for (int e = 0; e < 4; e++) s[j][e] = 0.f;

            const uint32_t baseK = sKs + (uint32_t)buf * (ABK * KSTR * 4);
#pragma unroll
            for (int k8 = 0; k8 < 8; k8++) {
                uint32_t bk[4][4];
#pragma unroll
                for (int p = 0; p < 4; p++) {
                    int nrow = (2 * p + (ql >> 1)) * 8 + rl;
                    int kc   = k8 * 8 + (ql & 1) * 4;
                    uint32_t addr = baseK + (uint32_t)(nrow * KSTR + kc) * 4;
                    asm volatile(
                        "ldmatrix.sync.aligned.m8n8.x4.shared.b16 {%0,%1,%2,%3}, [%4];"
                        : "=r"(bk[p][0]), "=r"(bk[p][1]), "=r"(bk[p][2]), "=r"(bk[p][3])
                        : "r"(addr));
                }
#pragma unroll
                for (int j = 0; j < 8; j++) {
                    uint32_t b0 = bk[j >> 1][(j & 1) * 2];
                    uint32_t b1 = bk[j >> 1][(j & 1) * 2 + 1];
                    asm volatile(
                        "mma.sync.aligned.m16n8k8.row.col.f32.tf32.tf32.f32 "
                        "{%0,%1,%2,%3}, {%4,%5,%6,%7}, {%8,%9}, {%0,%1,%2,%3};"
                        : "+f"(s[j][0]), "+f"(s[j][1]), "+f"(s[j][2]), "+f"(s[j][3])
                        : "r"(__float_as_uint(qf[k8][0])), "r"(__float_as_uint(qf[k8][1])),
                          "r"(__float_as_uint(qf[k8][2])), "r"(__float_as_uint(qf[k8][3])),
                          "r"(b0), "r"(b1));
                }
            }

            const bool need_mask = (k0 + 63 > wq0);
            float rmax0 = -1e30f, rmax1 = -1e30f;
#pragma unroll
            for (int j = 0; j < 8; j++) {
#pragma unroll
                for (int e = 0; e < 2; e++) {
                    float v0 = s[j][e]     * 0.125f;
                    float v1 = s[j][2 + e] * 0.125f;
                    if (need_mask) {
                        int col = k0 + j * 8 + 2 * c + e;
                        if (col > wq0 + r)     v0 = -1e30f;
                        if (col > wq0 + r + 8) v1 = -1e30f;
                    }
                    s[j][e] = v0; s[j][2 + e] = v1;
                    rmax0 = fmaxf(rmax0, v0);
                    rmax1 = fmaxf(rmax1, v1);
                }
            }
            rmax0 = fmaxf(rmax0, __shfl_xor_sync(0xffffffffu, rmax0, 1));
            rmax0 = fmaxf(rmax0, __shfl_xor_sync(0xffffffffu, rmax0, 2));
            rmax1 = fmaxf(rmax1, __shfl_xor_sync(0xffffffffu, rmax1, 1));
            rmax1 = fmaxf(rmax1, __shfl_xor_sync(0xffffffffu, rmax1, 2));

            float mn0 = fmaxf(m0, rmax0), mn1 = fmaxf(m1, rmax1);
            float corr0 = __expf(m0 - mn0), corr1 = __expf(m1 - mn1);
            m0 = mn0; m1 = mn1;

            float ls0 = 0.f, ls1 = 0.f;
#pragma unroll
            for (int j = 0; j < 8; j++) {
                s[j][0] = __expf(s[j][0] - mn0);
                s[j][1] = __expf(s[j][1] - mn0);
                s[j][2] = __expf(s[j][2] - mn1);
                s[j][3] = __expf(s[j][3] - mn1);
                ls0 += s[j][0] + s[j][1];
                ls1 += s[j][2] + s[j][3];
            }
            l0 = l0 * corr0 + ls0;
            l1 = l1 * corr1 + ls1;
#pragma unroll
            for (int j = 0; j < 8; j++) {
                o[j][0] *= corr0; o[j][1] *= corr0;
                o[j][2] *= corr1; o[j][3] *= corr1;
            }

#pragma unroll
            for (int kk = 0; kk < 4; kk++) {
                uint32_t a0 = pack_half2(s[2*kk][0],   s[2*kk][1]);
                uint32_t a1 = pack_half2(s[2*kk][2],   s[2*kk][3]);
                uint32_t a2 = pack_half2(s[2*kk+1][0], s[2*kk+1][1]);
                uint32_t a3 = pack_half2(s[2*kk+1][2], s[2*kk+1][3]);
#pragma unroll
                for (int jj = 0; jj < 4; jj++) {
                    uint32_t addr = sVs + (uint32_t)buf * (ABK * VSTR * 2)
                        + (uint32_t)((kk * 16 + (lane & 15)) * VSTR
                                     + jj * 16 + (lane >> 4) * 8) * 2;
                    uint32_t v0, v1, v2, v3;
                    asm volatile(
                        "ldmatrix.sync.aligned.m8n8.x4.trans.shared.b16 {%0,%1,%2,%3}, [%4];"
                        : "=r"(v0), "=r"(v1), "=r"(v2), "=r"(v3) : "r"(addr));
                    asm volatile(
                        "mma.sync.aligned.m16n8k16.row.col.f32.f16.f16.f32 "
                        "{%0,%1,%2,%3}, {%4,%5,%6,%7}, {%8,%9}, {%0,%1,%2,%3};"
                        : "+f"(o[2*jj][0]), "+f"(o[2*jj][1]), "+f"(o[2*jj][2]), "+f"(o[2*jj][3])
                        : "r"(a0), "r"(a1), "r"(a2), "r"(a3), "r"(v0), "r"(v1));
                    asm volatile(
                        "mma.sync.aligned.m16n8k16.row.col.f32.f16.f16.f32 "
                        "{%0,%1,%2,%3}, {%4,%5,%6,%7}, {%8,%9}, {%0,%1,%2,%3};"
                        : "+f"(o[2*jj+1][0]), "+f"(o[2*jj+1][1]), "+f"(o[2*jj+1][2]), "+f"(o[2*jj+1][3])
                        : "r"(a0), "r"(a1), "r"(a2), "r"(a3), "r"(v2), "r"(v3));
                }
            }
        }
        __syncthreads();
        buf ^= 1;
    }

    l0 += __shfl_xor_sync(0xffffffffu, l0, 1);
    l0 += __shfl_xor_sync(0xffffffffu, l0, 2);
    l1 += __shfl_xor_sync(0xffffffffu, l1, 1);
    l1 += __shfl_xor_sync(0xffffffffu, l1, 2);
    const float inv0 = 1.f / l0, inv1 = 1.f / l1;

    float* o0p = O + ((size_t)(b * Ss) + wq0 + r) * Dd + h * HD;
    float* o1p = o0p + 8 * (size_t)Dd;
#pragma unroll
    for (int j = 0; j < 8; j++) {
        int col = j * 8 + 2 * c;
        *(float2*)&o0p[col] = make_float2(to_tf32(o[j][0] * inv0),
                                          to_tf32(o[j][1] * inv0));
        *(float2*)&o1p[col] = make_float2(to_tf32(o[j][2] * inv1),
                                          to_tf32(o[j][3] * inv1));
    }
}

// ---------------------------------------------------------------------------
// Launch
// ---------------------------------------------------------------------------
extern "C" void kernel_launch(void* const* d_in, const int* in_sizes, int n_in,
                              void* d_out, int out_size)
{
    const float* x       = (const float*)d_in[0];
    const float* Wq      = (const float*)d_in[1];
    const float* Wk      = (const float*)d_in[2];
    const float* Wv      = (const float*)d_in[3];
    const float* Wq_ded  = (const float*)d_in[4];
    const float* Wk_ded  = (const float*)d_in[5];
    const float* Wv_ded  = (const float*)d_in[6];
    const float* Wo      = (const float*)d_in[7];

    float* out_o = (float*)d_out;
    float* out_k = out_o + ELEM;
    float* out_v = out_k + ELEM;

    float *qbuf = nullptr, *abuf = nullptr, *xt = nullptr, *wt = nullptr;
    cudaGetSymbolAddress((void**)&qbuf, g_q);
    cudaGetSymbolAddress((void**)&abuf, g_attn);
    cudaGetSymbolAddress((void**)&xt,   g_xt);
    cudaGetSymbolAddress((void**)&wt,   g_wt);
    float* wtq = wt;
    float* wtk = wt + (size_t)Dd * Dd;
    float* wtv = wt + 2 * (size_t)Dd * Dd;
    float* wto = wt + 3 * (size_t)Dd * Dd;

    cudaFuncSetAttribute(tf32_gemm_kernel,
                         cudaFuncAttributeMaxDynamicSharedMemorySize, GEMM_SMEM);
    cudaFuncSetAttribute(attn_tc_kernel,
                         cudaFuncAttributeMaxDynamicSharedMemorySize, ATTN_SMEM);

    // 0) round x to tf32; transpose+round the 4 weight matrices
    round_tf32_kernel<<<2048, 256>>>(x, xt, (int)(ELEM / 4));
    dim3 tg(32, 32), tb(32, 8);
    transpose_tf32_kernel<<<tg, tb>>>(Wq, wtq);
    transpose_tf32_kernel<<<tg, tb>>>(Wk, wtk);
    transpose_tf32_kernel<<<tg, tb>>>(Wv, wtv);
    transpose_tf32_kernel<<<tg, tb>>>(Wo, wto);

    // 1) fused Q/K/V shared projections
    dim3 gg3(Dd / GBN, TOK / GBM, 3);   // (4, 64, 3)
    tf32_gemm_kernel<<<gg3, 256, GEMM_SMEM>>>(
        xt, wtq, wtk, wtv, qbuf, out_k, out_v, Dd);

    // 2) dedicated-weight rows
    dim3 dg(16, Nn, 3);
    ded_proj_kernel<<<dg, 256>>>(x, Wq_ded, Wk_ded, Wv_ded, qbuf, out_k, out_v);

    // 3) tensor-core causal attention
    dim3 ag(Ss / ABQ, Hh, Bb);
    attn_tc_kernel<<<ag, 256, ATTN_SMEM>>>(qbuf, out_k, out_v, abuf);

    // 4) output projection
    dim3 gg1(Dd / GBN, TOK / GBM, 1);
    tf32_gemm_kernel<<<gg1, 256, GEMM_SMEM>>>(
        abuf, wto, wto, wto, out_o, out_o, out_o, Dd);
}

// round 8
// speedup vs baseline: 7.5505x; 1.2774x over previous
#include <cuda_runtime.h>
#include <cuda_bf16.h>
#include <cuda_fp16.h>
#include <math.h>
#include <cstdint>

// Problem constants
#define Bb   8
#define Ss   1024
#define Dd   1024
#define Hh   16
#define HD   64
#define Nn   16
#define TOK  (Bb*Ss)              // 8192
#define ELEM ((size_t)Bb*Ss*Dd)   // 8388608

// Scratch (allocation-free rule: device globals)
__device__ float  g_q[ELEM];                 // fp32 q for attention
__device__ __half g_xh[ELEM];                // fp16 x
__device__ __half g_wth[4 * Dd * Dd];        // fp16 transposed Wq,Wk,Wv,Wo
__device__ __half g_ah[ELEM];                // fp16 attention output

__device__ __forceinline__ uint32_t pack_half2(float a, float b) {
    uint32_t r;
    asm("cvt.rn.f16x2.f32 %0, %2, %1;" : "=r"(r) : "f"(a), "f"(b));
    return r;   // low half = a, high half = b
}

// ---------------------------------------------------------------------------
// Elementwise fp32 -> fp16 (x -> xh)
// ---------------------------------------------------------------------------
__global__ __launch_bounds__(256) void cvt_half_kernel(
    const float* __restrict__ in, __half* __restrict__ out, int n4)
{
    int i = blockIdx.x * blockDim.x + threadIdx.x;
    int stride = gridDim.x * blockDim.x;
    for (; i < n4; i += stride) {
        float4 v = ((const float4*)in)[i];
        __half2 h0 = __floats2half2_rn(v.x, v.y);
        __half2 h1 = __floats2half2_rn(v.z, v.w);
        ((__half2*)out)[2 * i]     = h0;
        ((__half2*)out)[2 * i + 1] = h1;
    }
}

// ---------------------------------------------------------------------------
// W transpose + fp16 convert: out[n][k] = half(in[k][n]), 1024x1024
// ---------------------------------------------------------------------------
__global__ __launch_bounds__(256) void transpose_h_kernel(
    const float* __restrict__ in, __half* __restrict__ out)
{
    __shared__ float t[32][33];
    int x = blockIdx.x * 32 + threadIdx.x;
    int y = blockIdx.y * 32 + threadIdx.y;
#pragma unroll
    for (int j = 0; j < 32; j += 8)
        t[threadIdx.y + j][threadIdx.x] = in[(size_t)(y + j) * Dd + x];
    __syncthreads();
    x = blockIdx.y * 32 + threadIdx.x;
    y = blockIdx.x * 32 + threadIdx.y;
#pragma unroll
    for (int j = 0; j < 32; j += 8)
        out[(size_t)(y + j) * Dd + x] = __float2half_rn(t[threadIdx.x][threadIdx.y + j]);
}

// ---------------------------------------------------------------------------
// fp16 tensor-core GEMM: C[M,Nc] = A[M,K] @ Wt[Nc,K]^T, fp32 accumulate.
// A fp16 [m][k]; Wt fp16 [n][k] pre-transposed. CTA tile 128x256, GBK=32,
// 256 threads, warps 2m x 4n (64x64), mma.m16n8k16.f16, 3-stage cp.async.
// ---------------------------------------------------------------------------
#define GBM 128
#define GBN 256
#define GBK 32
#define ASTR 40      // halves per smem row (32 data + 8 pad); 80B rows
#define NSTAGE 3
#define GEMM_SMEM (NSTAGE * (GBM + GBN) * ASTR * 2)   // 92160 B

__global__ void __launch_bounds__(256, 1)
h_gemm_kernel(const __half* __restrict__ A,
              const __half* __restrict__ Wt0, const __half* __restrict__ Wt1,
              const __half* __restrict__ Wt2,
              float* __restrict__ C0, float* __restrict__ C1,
              float* __restrict__ C2, int K)
{
    extern __shared__ __half smemh[];
    __half* As = smemh;                          // [NSTAGE][GBM*ASTR]
    __half* Bs = smemh + NSTAGE * GBM * ASTR;    // [NSTAGE][GBN*ASTR]

    const __half* Wt = (blockIdx.z == 0) ? Wt0 : (blockIdx.z == 1 ? Wt1 : Wt2);
    float* C         = (blockIdx.z == 0) ? C0  : (blockIdx.z == 1 ? C1  : C2);

    const int tid  = threadIdx.x;
    const int lane = tid & 31;
    const int wid  = tid >> 5;
    const int wm   = (wid & 1) * 64;
    const int wn   = (wid >> 1) * 64;
    const int m0   = blockIdx.y * GBM;
    const int n0   = blockIdx.x * GBN;

    const uint32_t sA = (uint32_t)__cvta_generic_to_shared(As);
    const uint32_t sB = (uint32_t)__cvta_generic_to_shared(Bs);

    float acc[4][8][4];
#pragma unroll
    for (int mf = 0; mf < 4; mf++)
#pragma unroll
        for (int nf = 0; nf < 8; nf++)
#pragma unroll
            for (int r = 0; r < 4; r++) acc[mf][nf][r] = 0.f;

    const __half* Abase = A + (size_t)m0 * K;
    const __half* Bbase = Wt + (size_t)n0 * K;

    auto load_tile = [&](int k0, int st) {
        uint32_t dstA = sA + (uint32_t)st * (GBM * ASTR * 2);
#pragma unroll
        for (int j = 0; j < 2; j++) {             // 128 rows x 2 chunks(16B)
            int g = tid + 256 * j;
            int m = g >> 2, c = g & 3;
            const __half* src = Abase + (size_t)m * K + k0 + c * 8;
            asm volatile("cp.async.ca.shared.global [%0], [%1], 16;\n"
                         :: "r"(dstA + (uint32_t)(m * ASTR + c * 8) * 2), "l"(src));
        }
        uint32_t dstB = sB + (uint32_t)st * (GBN * ASTR * 2);
#pragma unroll
        for (int j = 0; j < 4; j++) {             // 256 rows x 2 chunks? no: 256 rows x 4? 256*4=1024 chunks
            int g = tid + 256 * j;
            int n = g >> 2, c = g & 3;
            const __half* src = Bbase + (size_t)n * K + k0 + c * 8;
            asm volatile("cp.async.ca.shared.global [%0], [%1], 16;\n"
                         :: "r"(dstB + (uint32_t)(n * ASTR + c * 8) * 2), "l"(src));
        }
    };

    const int ql = lane >> 3, rl = lane & 7;

    auto compute = [&](int st) {
        const uint32_t baseA = sA + (uint32_t)st * (GBM * ASTR * 2);
        const uint32_t baseB = sB + (uint32_t)st * (GBN * ASTR * 2);
#pragma unroll
        for (int t = 0; t < 2; t++) {            // two k16 steps per 32-k tile
            uint32_t a[4][4];
#pragma unroll
            for (int mf = 0; mf < 4; mf++) {
                int mrow = wm + mf * 16 + rl + (ql & 1) * 8;
                int kc   = t * 16 + (ql >> 1) * 8;
                uint32_t addr = baseA + (uint32_t)(mrow * ASTR + kc) * 2;
                asm volatile(
                    "ldmatrix.sync.aligned.m8n8.x4.shared.b16 {%0,%1,%2,%3}, [%4];"
                    : "=r"(a[mf][0]), "=r"(a[mf][1]), "=r"(a[mf][2]), "=r"(a[mf][3])
                    : "r"(addr));
            }
            uint32_t b[4][4];
#pragma unroll
            for (int p = 0; p < 4; p++) {
                int nrow = wn + (2 * p + (ql >> 1)) * 8 + rl;
                int kc   = t * 16 + (ql & 1) * 8;
                uint32_t addr = baseB + (uint32_t)(nrow * ASTR + kc) * 2;
                asm volatile(
                    "ldmatrix.sync.aligned.m8n8.x4.shared.b16 {%0,%1,%2,%3}, [%4];"
                    : "=r"(b[p][0]), "=r"(b[p][1]), "=r"(b[p][2]), "=r"(b[p][3])
                    : "r"(addr));
            }
#pragma unroll
            for (int mf = 0; mf < 4; mf++)
#pragma unroll
                for (int nf = 0; nf < 8; nf++) {
                    uint32_t b0 = b[nf >> 1][(nf & 1) * 2];
                    uint32_t b1 = b[nf >> 1][(nf & 1) * 2 + 1];
                    asm volatile(
                        "mma.sync.aligned.m16n8k16.row.col.f32.f16.f16.f32 "
                        "{%0,%1,%2,%3}, {%4,%5,%6,%7}, {%8,%9}, {%0,%1,%2,%3};"
                        : "+f"(acc[mf][nf][0]), "+f"(acc[mf][nf][1]),
                          "+f"(acc[mf][nf][2]), "+f"(acc[mf][nf][3])
                        : "r"(a[mf][0]), "r"(a[mf][1]), "r"(a[mf][2]), "r"(a[mf][3]),
                          "r"(b0), "r"(b1));
                }
        }
    };

    // Prologue: stages 0,1 hold k-tiles 0,1
    load_tile(0, 0);
    asm volatile("cp.async.commit_group;");
    load_tile(GBK, 1);
    asm volatile("cp.async.commit_group;");

    // One group committed per iteration (empty at tail) so wait_group 1 at
    // iter i guarantees tile i. Prefetch stage (i+2)%3 was consumed at i-1,
    // protected by the top-of-loop __syncthreads().
    const int niter = K / GBK;
    for (int i = 0; i < niter; i++) {
        asm volatile("cp.async.wait_group 1;");
        __syncthreads();
        if ((i + 2) * GBK < K)
            load_tile((i + 2) * GBK, (i + 2) % NSTAGE);
        asm volatile("cp.async.commit_group;");
        compute(i % NSTAGE);
    }

    // Epilogue (fp32)
#pragma unroll
    for (int mf = 0; mf < 4; mf++) {
        int row = m0 + wm + mf * 16 + (lane >> 2);
#pragma unroll
        for (int nf = 0; nf < 8; nf++) {
            int col = n0 + wn + nf * 8 + (lane & 3) * 2;
            *(float2*)&C[(size_t)row * Dd + col] =
                make_float2(acc[mf][nf][0], acc[mf][nf][1]);
            *(float2*)&C[(size_t)(row + 8) * Dd + col] =
                make_float2(acc[mf][nf][2], acc[mf][nf][3]);
        }
    }
}

// ---------------------------------------------------------------------------
// Dedicated projection (fused q/k/v) — full fp32, unchanged
// ---------------------------------------------------------------------------
__global__ __launch_bounds__(256) void ded_proj_kernel(
    const float* __restrict__ x,
    const float* __restrict__ Wq_ded, const float* __restrict__ Wk_ded,
    const float* __restrict__ Wv_ded,
    float* __restrict__ qb, float* __restrict__ kb, float* __restrict__ vb)
{
    __shared__ float sm[8192];
    const int n   = blockIdx.y;
    const int o0  = blockIdx.x * 64;
    const int tid = threadIdx.x;
    const float* Wd = (blockIdx.z == 0) ? Wq_ded : (blockIdx.z == 1 ? Wk_ded : Wv_ded);
    float* out      = (blockIdx.z == 0) ? qb     : (blockIdx.z == 1 ? kb     : vb);

    for (int i = tid; i < Bb * Dd; i += 256) {
        int b = i >> 10, k = i & 1023;
        sm[i] = x[((size_t)b * Ss + n) * Dd + k];
    }
    __syncthreads();

    const int of4 = tid & 15;
    const int ks  = tid >> 4;
    const float* Wp = Wd + (size_t)n * Dd * Dd + (size_t)(ks * 64) * Dd + o0 + of4 * 4;

    float acc[8][4];
#pragma unroll
    for (int b = 0; b < 8; b++)
#pragma unroll
        for (int j = 0; j < 4; j++) acc[b][j] = 0.f;

#pragma unroll 4
    for (int kk = 0; kk < 64; kk++) {
        float4 w = *(const float4*)(Wp + (size_t)kk * Dd);
        int k = ks * 64 + kk;
#pragma unroll
        for (int b = 0; b < 8; b++) {
            float xv = sm[b * 1024 + k];
            acc[b][0] += xv * w.x; acc[b][1] += xv * w.y;
            acc[b][2] += xv * w.z; acc[b][3] += xv * w.w;
        }
    }
    __syncthreads();

#pragma unroll
    for (int b = 0; b < 8; b++)
        *(float4*)&sm[ks * 512 + b * 64 + of4 * 4] =
            make_float4(acc[b][0], acc[b][1], acc[b][2], acc[b][3]);
    __syncthreads();

    for (int p = tid; p < 512; p += 256) {
        int b = p >> 6, ol = p & 63;
        float s = 0.f;
#pragma unroll
        for (int k2 = 0; k2 < 16; k2++) s += sm[k2 * 512 + p];
        out[((size_t)b * Ss + n) * Dd + o0 + ol] = s;
    }
}

// ---------------------------------------------------------------------------
// Tensor-core causal flash attention. QK tf32, PV fp16.
// Epilogue now writes fp16 (A operand for the O-projection GEMM).
// ---------------------------------------------------------------------------
#define ABQ 128
#define ABK 64
#define KSTR 68
#define VSTR 72
#define ATTN_SMEM (2*ABK*KSTR*4 + 2*ABK*VSTR*2)

__global__ __launch_bounds__(256) void attn_tc_kernel(
    const float* __restrict__ Q, const float* __restrict__ Kt,
    const float* __restrict__ Vt, __half* __restrict__ OH)
{
    extern __shared__ char asmem[];
    float*  Ks = (float*)asmem;
    __half* Vs = (__half*)(asmem + 2 * ABK * KSTR * 4);

    const int b   = blockIdx.z;
    const int h   = blockIdx.y;
    const int q0  = blockIdx.x * ABQ;
    const int tid = threadIdx.x;
    const int lane = tid & 31;
    const int wid  = tid >> 5;
    const int wq0  = q0 + wid * 16;
    const int r = lane >> 2;
    const int c = lane & 3;

    const uint32_t sKs = (uint32_t)__cvta_generic_to_shared(Ks);
    const uint32_t sVs = (uint32_t)__cvta_generic_to_shared(Vs);

    float qf[8][4];
    {
        const float* q0p = Q + ((size_t)(b * Ss) + wq0 + r) * Dd + h * HD;
        const float* q1p = q0p + 8 * (size_t)Dd;
#pragma unroll
        for (int k8 = 0; k8 < 8; k8++) {
            qf[k8][0] = q0p[k8 * 8 + c];
            qf[k8][1] = q1p[k8 * 8 + c];
            qf[k8][2] = q0p[k8 * 8 + c + 4];
            qf[k8][3] = q1p[k8 * 8 + c + 4];
        }
    }

    const float* Kbase = Kt + (size_t)(b * Ss) * Dd + h * HD;
    const float* Vbase = Vt + (size_t)(b * Ss) * Dd + h * HD;

    auto load_k = [&](int k0, int buf) {
        uint32_t dst = sKs + (uint32_t)buf * (ABK * KSTR * 4);
#pragma unroll
        for (int j = 0; j < 4; j++) {
            int g = tid + 256 * j;
            int row = g >> 4, c4 = g & 15;
            const float* src = Kbase + (size_t)(k0 + row) * Dd + c4 * 4;
            asm volatile("cp.async.ca.shared.global [%0], [%1], 16;\n"
                         :: "r"(dst + (uint32_t)(row * KSTR + c4 * 4) * 4), "l"(src));
        }
    };
    auto load_v = [&](int k0, int buf) {
        __half* dstV = Vs + buf * (ABK * VSTR);
#pragma unroll
        for (int j = 0; j < 4; j++) {
            int g = tid + 256 * j;
            int row = g >> 4, c4 = g & 15;
            float4 v = *(const float4*)(Vbase + (size_t)(k0 + row) * Dd + c4 * 4);
            __half2 h0 = __floats2half2_rn(v.x, v.y);
            __half2 h1 = __floats2half2_rn(v.z, v.w);
            *(__half2*)&dstV[row * VSTR + c4 * 4]     = h0;
            *(__half2*)&dstV[row * VSTR + c4 * 4 + 2] = h1;
        }
    };

    float o[8][4];
#pragma unroll
    for (int j = 0; j < 8; j++)
#pragma unroll
        for (int e = 0; e < 4; e++) o[j][e] = 0.f;
    float m0 = -1e30f, m1 = -1e30f, l0 = 0.f, l1 = 0.f;

    const int kend = q0 + ABQ;
    load_k(0, 0);
    asm volatile("cp.async.commit_group;");
    load_v(0, 0);

    int buf = 0;
    const int ql = lane >> 3, rl = lane & 7;

    for (int k0 = 0; k0 < kend; k0 += ABK) {
        asm volatile("cp.async.wait_group 0;");
        __syncthreads();
        if (k0 + ABK < kend) {
            load_k(k0 + ABK, buf ^ 1);
            asm volatile("cp.async.commit_group;");
            load_v(k0 + ABK, buf ^ 1);
        }

        if (k0 <= wq0 + 15) {
            float s[8][4];
#pragma unroll
            for (int j = 0; j < 8; j++)
#pragma unroll
                for (int e = 0; e < 4; e++) s[j][e] = 0.f;

            const uint32_t baseK = sKs + (uint32_t)buf * (ABK * KSTR * 4);
#pragma unroll
            for (int k8 = 0; k8 < 8; k8++) {
                uint32_t bk[4][4];
#pragma unroll
                for (int p = 0; p < 4; p++) {
                    int nrow = (2 * p + (ql >> 1)) * 8 + rl;
                    int kc   = k8 * 8 + (ql & 1) * 4;
                    uint32_t addr = baseK + (uint32_t)(nrow * KSTR + kc) * 4;
                    asm volatile(
                        "ldmatrix.sync.aligned.m8n8.x4.shared.b16 {%0,%1,%2,%3}, [%4];"
                        : "=r"(bk[p][0]), "=r"(bk[p][1]), "=r"(bk[p][2]), "=r"(bk[p][3])
                        : "r"(addr));
                }
#pragma unroll
                for (int j = 0; j < 8; j++) {
                    uint32_t b0 = bk[j >> 1][(j & 1) * 2];
                    uint32_t b1 = bk[j >> 1][(j & 1) * 2 + 1];
                    asm volatile(
                        "mma.sync.aligned.m16n8k8.row.col.f32.tf32.tf32.f32 "
                        "{%0,%1,%2,%3}, {%4,%5,%6,%7}, {%8,%9}, {%0,%1,%2,%3};"
                        : "+f"(s[j][0]), "+f"(s[j][1]), "+f"(s[j][2]), "+f"(s[j][3])
                        : "r"(__float_as_uint(qf[k8][0])), "r"(__float_as_uint(qf[k8][1])),
                          "r"(__float_as_uint(qf[k8][2])), "r"(__float_as_uint(qf[k8][3])),
                          "r"(b0), "r"(b1));
                }
            }

            const bool need_mask = (k0 + 63 > wq0);
            float rmax0 = -1e30f, rmax1 = -1e30f;
#pragma unroll
            for (int j = 0; j < 8; j++) {
#pragma unroll
                for (int e = 0; e < 2; e++) {
                    float v0 = s[j][e]     * 0.125f;
                    float v1 = s[j][2 + e] * 0.125f;
                    if (need_mask) {
                        int col = k0 + j * 8 + 2 * c + e;
                        if (col > wq0 + r)     v0 = -1e30f;
                        if (col > wq0 + r + 8) v1 = -1e30f;
                    }
                    s[j][e] = v0; s[j][2 + e] = v1;
                    rmax0 = fmaxf(rmax0, v0);
                    rmax1 = fmaxf(rmax1, v1);
                }
            }
            rmax0 = fmaxf(rmax0, __shfl_xor_sync(0xffffffffu, rmax0, 1));
            rmax0 = fmaxf(rmax0, __shfl_xor_sync(0xffffffffu, rmax0, 2));
            rmax1 = fmaxf(rmax1, __shfl_xor_sync(0xffffffffu, rmax1, 1));
            rmax1 = fmaxf(rmax1, __shfl_xor_sync(0xffffffffu, rmax1, 2));

            float mn0 = fmaxf(m0, rmax0), mn1 = fmaxf(m1, rmax1);
            float corr0 = __expf(m0 - mn0), corr1 = __expf(m1 - mn1);
            m0 = mn0; m1 = mn1;

            float ls0 = 0.f, ls1 = 0.f;
#pragma unroll
            for (int j = 0; j < 8; j++) {
                s[j][0] = __expf(s[j][0] - mn0);
                s[j][1] = __expf(s[j][1] - mn0);
                s[j][2] = __expf(s[j][2] - mn1);
                s[j][3] = __expf(s[j][3] - mn1);
                ls0 += s[j][0] + s[j][1];
                ls1 += s[j][2] + s[j][3];
            }
            l0 = l0 * corr0 + ls0;
            l1 = l1 * corr1 + ls1;
#pragma unroll
            for (int j = 0; j < 8; j++) {
                o[j][0] *= corr0; o[j][1] *= corr0;
                o[j][2] *= corr1; o[j][3] *= corr1;
            }

#pragma unroll
            for (int kk = 0; kk < 4; kk++) {
                uint32_t a0 = pack_half2(s[2*kk][0],   s[2*kk][1]);
                uint32_t a1 = pack_half2(s[2*kk][2],   s[2*kk][3]);
                uint32_t a2 = pack_half2(s[2*kk+1][0], s[2*kk+1][1]);
                uint32_t a3 = pack_half2(s[2*kk+1][2], s[2*kk+1][3]);
#pragma unroll
                for (int jj = 0; jj < 4; jj++) {
                    uint32_t addr = sVs + (uint32_t)buf * (ABK * VSTR * 2)
                        + (uint32_t)((kk * 16 + (lane & 15)) * VSTR
                                     + jj * 16 + (lane >> 4) * 8) * 2;
                    uint32_t v0, v1, v2, v3;
                    asm volatile(
                        "ldmatrix.sync.aligned.m8n8.x4.trans.shared.b16 {%0,%1,%2,%3}, [%4];"
                        : "=r"(v0), "=r"(v1), "=r"(v2), "=r"(v3) : "r"(addr));
                    asm volatile(
                        "mma.sync.aligned.m16n8k16.row.col.f32.f16.f16.f32 "
                        "{%0,%1,%2,%3}, {%4,%5,%6,%7}, {%8,%9}, {%0,%1,%2,%3};"
                        : "+f"(o[2*jj][0]), "+f"(o[2*jj][1]), "+f"(o[2*jj][2]), "+f"(o[2*jj][3])
                        : "r"(a0), "r"(a1), "r"(a2), "r"(a3), "r"(v0), "r"(v1));
                    asm volatile(
                        "mma.sync.aligned.m16n8k16.row.col.f32.f16.f16.f32 "
                        "{%0,%1,%2,%3}, {%4,%5,%6,%7}, {%8,%9}, {%0,%1,%2,%3};"
                        : "+f"(o[2*jj+1][0]), "+f"(o[2*jj+1][1]), "+f"(o[2*jj+1][2]), "+f"(o[2*jj+1][3])
                        : "r"(a0), "r"(a1), "r"(a2), "r"(a3), "r"(v2), "r"(v3));
                }
            }
        }
        __syncthreads();
        buf ^= 1;
    }

    l0 += __shfl_xor_sync(0xffffffffu, l0, 1);
    l0 += __shfl_xor_sync(0xffffffffu, l0, 2);
    l1 += __shfl_xor_sync(0xffffffffu, l1, 1);
    l1 += __shfl_xor_sync(0xffffffffu, l1, 2);
    const float inv0 = 1.f / l0, inv1 = 1.f / l1;

    __half* o0p = OH + ((size_t)(b * Ss) + wq0 + r) * Dd + h * HD;
    __half* o1p = o0p + 8 * (size_t)Dd;
#pragma unroll
    for (int j = 0; j < 8; j++) {
        int col = j * 8 + 2 * c;
        *(__half2*)&o0p[col] = __floats2half2_rn(o[j][0] * inv0, o[j][1] * inv0);
        *(__half2*)&o1p[col] = __floats2half2_rn(o[j][2] * inv1, o[j][3] * inv1);
    }
}

// ---------------------------------------------------------------------------
// Launch
// ---------------------------------------------------------------------------
extern "C" void kernel_launch(void* const* d_in, const int* in_sizes, int n_in,
                              void* d_out, int out_size)
{
    const float* x       = (const float*)d_in[0];
    const float* Wq      = (const float*)d_in[1];
    const float* Wk      = (const float*)d_in[2];
    const float* Wv      = (const float*)d_in[3];
    const float* Wq_ded  = (const float*)d_in[4];
    const float* Wk_ded  = (const float*)d_in[5];
    const float* Wv_ded  = (const float*)d_in[6];
    const float* Wo      = (const float*)d_in[7];

    float* out_o = (float*)d_out;
    float* out_k = out_o + ELEM;
    float* out_v = out_k + ELEM;

    float  *qbuf = nullptr;
    __half *xh = nullptr, *wth = nullptr, *ah = nullptr;
    cudaGetSymbolAddress((void**)&qbuf, g_q);
    cudaGetSymbolAddress((void**)&xh,   g_xh);
    cudaGetSymbolAddress((void**)&wth,  g_wth);
    cudaGetSymbolAddress((void**)&ah,   g_ah);
    __half* wtq = wth;
    __half* wtk = wth + (size_t)Dd * Dd;
    __half* wtv = wth + 2 * (size_t)Dd * Dd;
    __half* wto = wth + 3 * (size_t)Dd * Dd;

    cudaFuncSetAttribute(h_gemm_kernel,
                         cudaFuncAttributeMaxDynamicSharedMemorySize, GEMM_SMEM);
    cudaFuncSetAttribute(attn_tc_kernel,
                         cudaFuncAttributeMaxDynamicSharedMemorySize, ATTN_SMEM);

    // 0) x -> fp16; transpose+convert the 4 weight matrices
    cvt_half_kernel<<<2048, 256>>>(x, xh, (int)(ELEM / 4));
    dim3 tg(32, 32), tb(32, 8);
    transpose_h_kernel<<<tg, tb>>>(Wq, wtq);
    transpose_h_kernel<<<tg, tb>>>(Wk, wtk);
    transpose_h_kernel<<<tg, tb>>>(Wv, wtv);
    transpose_h_kernel<<<tg, tb>>>(Wo, wto);

    // 1) fused Q/K/V shared projections (fp16 in, fp32 out)
    dim3 gg3(Dd / GBN, TOK / GBM, 3);   // (4, 64, 3)
    h_gemm_kernel<<<gg3, 256, GEMM_SMEM>>>(
        xh, wtq, wtk, wtv, qbuf, out_k, out_v, Dd);

    // 2) dedicated-weight rows (full fp32)
    dim3 dg(16, Nn, 3);
    ded_proj_kernel<<<dg, 256>>>(x, Wq_ded, Wk_ded, Wv_ded, qbuf, out_k, out_v);

    // 3) tensor-core causal attention (fp16 output for O-proj)
    dim3 ag(Ss / ABQ, Hh, Bb);
    attn_tc_kernel<<<ag, 256, ATTN_SMEM>>>(qbuf, out_k, out_v, ah);

    // 4) output projection
    dim3 gg1(Dd / GBN, TOK / GBM, 1);
    h_gemm_kernel<<<gg1, 256, GEMM_SMEM>>>(
        ah, wto, wto, wto, out_o, out_o, out_o, Dd);
}

// round 9
// speedup vs baseline: 8.4302x; 1.1165x over previous
#include <cuda_runtime.h>
#include <cuda_bf16.h>
#include <cuda_fp16.h>
#include <math.h>
#include <cstdint>

// Problem constants
#define Bb   8
#define Ss   1024
#define Dd   1024
#define Hh   16
#define HD   64
#define Nn   16
#define TOK  (Bb*Ss)              // 8192
#define ELEM ((size_t)Bb*Ss*Dd)   // 8388608

// Scratch (allocation-free rule: device globals)
__device__ float  g_q[ELEM];                 // fp32 q (dead store target, keeps GEMM uniform)
__device__ __half g_xh[ELEM];                // fp16 x
__device__ __half g_wth[4 * Dd * Dd];        // fp16 transposed Wq,Wk,Wv,Wo
__device__ __half g_ah[ELEM];                // fp16 attention output
__device__ __half g_qh[ELEM];                // fp16 q for attention
__device__ __half g_kh[ELEM];                // fp16 k for attention
__device__ __half g_vh[ELEM];                // fp16 v for attention

__device__ __forceinline__ uint32_t pack_half2(float a, float b) {
    uint32_t r;
    asm("cvt.rn.f16x2.f32 %0, %2, %1;" : "=r"(r) : "f"(a), "f"(b));
    return r;   // low half = a, high half = b
}

// ---------------------------------------------------------------------------
// Elementwise fp32 -> fp16 (x -> xh)
// ---------------------------------------------------------------------------
__global__ __launch_bounds__(256) void cvt_half_kernel(
    const float* __restrict__ in, __half* __restrict__ out, int n4)
{
    int i = blockIdx.x * blockDim.x + threadIdx.x;
    int stride = gridDim.x * blockDim.x;
    for (; i < n4; i += stride) {
        float4 v = ((const float4*)in)[i];
        __half2 h0 = __floats2half2_rn(v.x, v.y);
        __half2 h1 = __floats2half2_rn(v.z, v.w);
        ((__half2*)out)[2 * i]     = h0;
        ((__half2*)out)[2 * i + 1] = h1;
    }
}

// ---------------------------------------------------------------------------
// W transpose + fp16 convert: out[n][k] = half(in[k][n]), 1024x1024
// ---------------------------------------------------------------------------
__global__ __launch_bounds__(256) void transpose_h_kernel(
    const float* __restrict__ in, __half* __restrict__ out)
{
    __shared__ float t[32][33];
    int x = blockIdx.x * 32 + threadIdx.x;
    int y = blockIdx.y * 32 + threadIdx.y;
#pragma unroll
    for (int j = 0; j < 32; j += 8)
        t[threadIdx.y + j][threadIdx.x] = in[(size_t)(y + j) * Dd + x];
    __syncthreads();
    x = blockIdx.y * 32 + threadIdx.x;
    y = blockIdx.x * 32 + threadIdx.y;
#pragma unroll
    for (int j = 0; j < 32; j += 8)
        out[(size_t)(y + j) * Dd + x] = __float2half_rn(t[threadIdx.x][threadIdx.y + j]);
}

// ---------------------------------------------------------------------------
// fp16 tensor-core GEMM: C[M,Nc] = A[M,K] @ Wt[Nc,K]^T, fp32 accumulate.
// Optional fused fp16 copy of the output (H0/H1/H2), for the attention path.
// ---------------------------------------------------------------------------
#define GBM 128
#define GBN 256
#define GBK 32
#define ASTR 40      // halves per smem row (32 data + 8 pad)
#define NSTAGE 3
#define GEMM_SMEM (NSTAGE * (GBM + GBN) * ASTR * 2)   // 92160 B

__global__ void __launch_bounds__(256, 1)
h_gemm_kernel(const __half* __restrict__ A,
              const __half* __restrict__ Wt0, const __half* __restrict__ Wt1,
              const __half* __restrict__ Wt2,
              float* __restrict__ C0, float* __restrict__ C1,
              float* __restrict__ C2,
              __half* __restrict__ H0, __half* __restrict__ H1,
              __half* __restrict__ H2, int K)
{
    extern __shared__ __half smemh[];
    __half* As = smemh;
    __half* Bs = smemh + NSTAGE * GBM * ASTR;

    const __half* Wt = (blockIdx.z == 0) ? Wt0 : (blockIdx.z == 1 ? Wt1 : Wt2);
    float* C         = (blockIdx.z == 0) ? C0  : (blockIdx.z == 1 ? C1  : C2);
    __half* Hc       = (blockIdx.z == 0) ? H0  : (blockIdx.z == 1 ? H1  : H2);

    const int tid  = threadIdx.x;
    const int lane = tid & 31;
    const int wid  = tid >> 5;
    const int wm   = (wid & 1) * 64;
    const int wn   = (wid >> 1) * 64;
    const int m0   = blockIdx.y * GBM;
    const int n0   = blockIdx.x * GBN;

    const uint32_t sA = (uint32_t)__cvta_generic_to_shared(As);
    const uint32_t sB = (uint32_t)__cvta_generic_to_shared(Bs);

    float acc[4][8][4];
#pragma unroll
    for (int mf = 0; mf < 4; mf++)
#pragma unroll
        for (int nf = 0; nf < 8; nf++)
#pragma unroll
            for (int r = 0; r < 4; r++) acc[mf][nf][r] = 0.f;

    const __half* Abase = A + (size_t)m0 * K;
    const __half* Bbase = Wt + (size_t)n0 * K;

    auto load_tile = [&](int k0, int st) {
        uint32_t dstA = sA + (uint32_t)st * (GBM * ASTR * 2);
#pragma unroll
        for (int j = 0; j < 2; j++) {
            int g = tid + 256 * j;
            int m = g >> 2, c = g & 3;
            const __half* src = Abase + (size_t)m * K + k0 + c * 8;
            asm volatile("cp.async.ca.shared.global [%0], [%1], 16;\n"
                         :: "r"(dstA + (uint32_t)(m * ASTR + c * 8) * 2), "l"(src));
        }
        uint32_t dstB = sB + (uint32_t)st * (GBN * ASTR * 2);
#pragma unroll
        for (int j = 0; j < 4; j++) {
            int g = tid + 256 * j;
            int n = g >> 2, c = g & 3;
            const __half* src = Bbase + (size_t)n * K + k0 + c * 8;
            asm volatile("cp.async.ca.shared.global [%0], [%1], 16;\n"
                         :: "r"(dstB + (uint32_t)(n * ASTR + c * 8) * 2), "l"(src));
        }
    };

    const int ql = lane >> 3, rl = lane & 7;

    auto compute = [&](int st) {
        const uint32_t baseA = sA + (uint32_t)st * (GBM * ASTR * 2);
        const uint32_t baseB = sB + (uint32_t)st * (GBN * ASTR * 2);
#pragma unroll
        for (int t = 0; t < 2; t++) {
            uint32_t a[4][4];
#pragma unroll
            for (int mf = 0; mf < 4; mf++) {
                int mrow = wm + mf * 16 + rl + (ql & 1) * 8;
                int kc   = t * 16 + (ql >> 1) * 8;
                uint32_t addr = baseA + (uint32_t)(mrow * ASTR + kc) * 2;
                asm volatile(
                    "ldmatrix.sync.aligned.m8n8.x4.shared.b16 {%0,%1,%2,%3}, [%4];"
                    : "=r"(a[mf][0]), "=r"(a[mf][1]), "=r"(a[mf][2]), "=r"(a[mf][3])
                    : "r"(addr));
            }
            uint32_t b[4][4];
#pragma unroll
            for (int p = 0; p < 4; p++) {
                int nrow = wn + (2 * p + (ql >> 1)) * 8 + rl;
                int kc   = t * 16 + (ql & 1) * 8;
                uint32_t addr = baseB + (uint32_t)(nrow * ASTR + kc) * 2;
                asm volatile(
                    "ldmatrix.sync.aligned.m8n8.x4.shared.b16 {%0,%1,%2,%3}, [%4];"
                    : "=r"(b[p][0]), "=r"(b[p][1]), "=r"(b[p][2]), "=r"(b[p][3])
                    : "r"(addr));
            }
#pragma unroll
            for (int mf = 0; mf < 4; mf++)
#pragma unroll
                for (int nf = 0; nf < 8; nf++) {
                    uint32_t b0 = b[nf >> 1][(nf & 1) * 2];
                    uint32_t b1 = b[nf >> 1][(nf & 1) * 2 + 1];
                    asm volatile(
                        "mma.sync.aligned.m16n8k16.row.col.f32.f16.f16.f32 "
                        "{%0,%1,%2,%3}, {%4,%5,%6,%7}, {%8,%9}, {%0,%1,%2,%3};"
                        : "+f"(acc[mf][nf][0]), "+f"(acc[mf][nf][1]),
                          "+f"(acc[mf][nf][2]), "+f"(acc[mf][nf][3])
                        : "r"(a[mf][0]), "r"(a[mf][1]), "r"(a[mf][2]), "r"(a[mf][3]),
                          "r"(b0), "r"(b1));
                }
        }
    };

    load_tile(0, 0);
    asm volatile("cp.async.commit_group;");
    load_tile(GBK, 1);
    asm volatile("cp.async.commit_group;");

    const int niter = K / GBK;
    for (int i = 0; i < niter; i++) {
        asm volatile("cp.async.wait_group 1;");
        __syncthreads();
        if ((i + 2) * GBK < K)
            load_tile((i + 2) * GBK, (i + 2) % NSTAGE);
        asm volatile("cp.async.commit_group;");
        compute(i % NSTAGE);
    }

    // Epilogue: fp32 always; fp16 copy when requested
#pragma unroll
    for (int mf = 0; mf < 4; mf++) {
        int row = m0 + wm + mf * 16 + (lane >> 2);
#pragma unroll
        for (int nf = 0; nf < 8; nf++) {
            int col = n0 + wn + nf * 8 + (lane & 3) * 2;
            *(float2*)&C[(size_t)row * Dd + col] =
                make_float2(acc[mf][nf][0], acc[mf][nf][1]);
            *(float2*)&C[(size_t)(row + 8) * Dd + col] =
                make_float2(acc[mf][nf][2], acc[mf][nf][3]);
            if (Hc) {
                *(uint32_t*)&Hc[(size_t)row * Dd + col] =
                    pack_half2(acc[mf][nf][0], acc[mf][nf][1]);
                *(uint32_t*)&Hc[(size_t)(row + 8) * Dd + col] =
                    pack_half2(acc[mf][nf][2], acc[mf][nf][3]);
            }
        }
    }
}

// ---------------------------------------------------------------------------
// Dedicated projection (fused q/k/v), fp32 compute; dual fp32+fp16 writes.
// ---------------------------------------------------------------------------
__global__ __launch_bounds__(256) void ded_proj_kernel(
    const float* __restrict__ x,
    const float* __restrict__ Wq_ded, const float* __restrict__ Wk_ded,
    const float* __restrict__ Wv_ded,
    float* __restrict__ qb, float* __restrict__ kb, float* __restrict__ vb,
    __half* __restrict__ qh, __half* __restrict__ kh, __half* __restrict__ vh)
{
    __shared__ float sm[8192];
    const int n   = blockIdx.y;
    const int o0  = blockIdx.x * 64;
    const int tid = threadIdx.x;
    const float* Wd = (blockIdx.z == 0) ? Wq_ded : (blockIdx.z == 1 ? Wk_ded : Wv_ded);
    float* out      = (blockIdx.z == 0) ? qb     : (blockIdx.z == 1 ? kb     : vb);
    __half* outh    = (blockIdx.z == 0) ? qh     : (blockIdx.z == 1 ? kh     : vh);

    for (int i = tid; i < Bb * Dd; i += 256) {
        int b = i >> 10, k = i & 1023;
        sm[i] = x[((size_t)b * Ss + n) * Dd + k];
    }
    __syncthreads();

    const int of4 = tid & 15;
    const int ks  = tid >> 4;
    const float* Wp = Wd + (size_t)n * Dd * Dd + (size_t)(ks * 64) * Dd + o0 + of4 * 4;

    float acc[8][4];
#pragma unroll
    for (int b = 0; b < 8; b++)
#pragma unroll
        for (int j = 0; j < 4; j++) acc[b][j] = 0.f;

#pragma unroll 4
    for (int kk = 0; kk < 64; kk++) {
        float4 w = *(const float4*)(Wp + (size_t)kk * Dd);
        int k = ks * 64 + kk;
#pragma unroll
        for (int b = 0; b < 8; b++) {
            float xv = sm[b * 1024 + k];
            acc[b][0] += xv * w.x; acc[b][1] += xv * w.y;
            acc[b][2] += xv * w.z; acc[b][3] += xv * w.w;
        }
    }
    __syncthreads();

#pragma unroll
    for (int b = 0; b < 8; b++)
        *(float4*)&sm[ks * 512 + b * 64 + of4 * 4] =
            make_float4(acc[b][0], acc[b][1], acc[b][2], acc[b][3]);
    __syncthreads();

    for (int p = tid; p < 512; p += 256) {
        int b = p >> 6, ol = p & 63;
        float s = 0.f;
#pragma unroll
        for (int k2 = 0; k2 < 16; k2++) s += sm[k2 * 512 + p];
        size_t idx = ((size_t)b * Ss + n) * Dd + o0 + ol;
        out[idx]  = s;
        outh[idx] = __float2half_rn(s);
    }
}

// ---------------------------------------------------------------------------
// Tensor-core causal flash attention — fully fp16 operands, fp32 softmax/acc.
// Q/K/V read as fp16 (produced by GEMM epilogue). QK and PV both m16n8k16.f16.
// ---------------------------------------------------------------------------
#define ABQ 128
#define ABK 64
#define KHSTR 72   // halves per K smem row (64 + 8 pad)
#define VSTR  72   // halves per V smem row
#define ATTN_SMEM (2*ABK*KHSTR*2 + 2*ABK*VSTR*2)   // 36864 B

__global__ __launch_bounds__(256) void attn_tc_kernel(
    const __half* __restrict__ Qh, const __half* __restrict__ Kh,
    const __half* __restrict__ Vh, __half* __restrict__ OH)
{
    extern __shared__ char asmem[];
    __half* Ks = (__half*)asmem;                           // [2][ABK*KHSTR]
    __half* Vs = (__half*)(asmem + 2 * ABK * KHSTR * 2);   // [2][ABK*VSTR]

    const int b   = blockIdx.z;
    const int h   = blockIdx.y;
    const int q0  = blockIdx.x * ABQ;
    const int tid = threadIdx.x;
    const int lane = tid & 31;
    const int wid  = tid >> 5;
    const int wq0  = q0 + wid * 16;
    const int r = lane >> 2;
    const int c = lane & 3;

    const uint32_t sKs = (uint32_t)__cvta_generic_to_shared(Ks);
    const uint32_t sVs = (uint32_t)__cvta_generic_to_shared(Vs);

    // Q fragments, canonical m16n8k16 fp16 A layout, 4 k16-steps.
    uint32_t qf[4][4];
    {
        const __half* q0p = Qh + ((size_t)(b * Ss) + wq0 + r) * Dd + h * HD;
        const __half* q1p = q0p + 8 * (size_t)Dd;
#pragma unroll
        for (int t = 0; t < 4; t++) {
            qf[t][0] = *(const uint32_t*)&q0p[t * 16 + 2 * c];
            qf[t][1] = *(const uint32_t*)&q1p[t * 16 + 2 * c];
            qf[t][2] = *(const uint32_t*)&q0p[t * 16 + 2 * c + 8];
            qf[t][3] = *(const uint32_t*)&q1p[t * 16 + 2 * c + 8];
        }
    }

    const __half* Kbase = Kh + (size_t)(b * Ss) * Dd + h * HD;
    const __half* Vbase = Vh + (size_t)(b * Ss) * Dd + h * HD;

    // 64 rows x 64 halves = 512 x 16B chunks per tile; 256 threads x 2
    auto load_k = [&](int k0, int buf) {
        uint32_t dst = sKs + (uint32_t)buf * (ABK * KHSTR * 2);
#pragma unroll
        for (int j = 0; j < 2; j++) {
            int g = tid + 256 * j;
            int row = g >> 3, c8 = g & 7;
            const __half* src = Kbase + (size_t)(k0 + row) * Dd + c8 * 8;
            asm volatile("cp.async.ca.shared.global [%0], [%1], 16;\n"
                         :: "r"(dst + (uint32_t)(row * KHSTR + c8 * 8) * 2), "l"(src));
        }
    };
    auto load_v = [&](int k0, int buf) {
        uint32_t dst = sVs + (uint32_t)buf * (ABK * VSTR * 2);
#pragma unroll
        for (int j = 0; j < 2; j++) {
            int g = tid + 256 * j;
            int row = g >> 3, c8 = g & 7;
            const __half* src = Vbase + (size_t)(k0 + row) * Dd + c8 * 8;
            asm volatile("cp.async.ca.shared.global [%0], [%1], 16;\n"
                         :: "r"(dst + (uint32_t)(row * VSTR + c8 * 8) * 2), "l"(src));
        }
    };

    float o[8][4];
#pragma unroll
    for (int j = 0; j < 8; j++)
#pragma unroll
        for (int e = 0; e < 4; e++) o[j][e] = 0.f;
    float m0 = -1e30f, m1 = -1e30f, l0 = 0.f, l1 = 0.f;

    const int kend = q0 + ABQ;
    load_k(0, 0);
    load_v(0, 0);
    asm volatile("cp.async.commit_group;");

    int buf = 0;
    const int ql = lane >> 3, rl = lane & 7;

    for (int k0 = 0; k0 < kend; k0 += ABK) {
        asm volatile("cp.async.wait_group 0;");
        __syncthreads();
        if (k0 + ABK < kend) {
            load_k(k0 + ABK, buf ^ 1);
            load_v(k0 + ABK, buf ^ 1);
            asm volatile("cp.async.commit_group;");
        }

        if (k0 <= wq0 + 15) {
            // ---- S = Q @ K^T (fp16, 4 k16-steps) ----
            float s[8][4];
#pragma unroll
            for (int j = 0; j < 8; j++)
#pragma unroll
                for (int e = 0; e < 4; e++) s[j][e] = 0.f;

            const uint32_t baseK = sKs + (uint32_t)buf * (ABK * KHSTR * 2);
#pragma unroll
            for (int t = 0; t < 4; t++) {
                uint32_t bk[4][4];
#pragma unroll
                for (int p = 0; p < 4; p++) {
                    int nrow = (2 * p + (ql >> 1)) * 8 + rl;
                    int kc   = t * 16 + (ql & 1) * 8;
                    uint32_t addr = baseK + (uint32_t)(nrow * KHSTR + kc) * 2;
                    asm volatile(
                        "ldmatrix.sync.aligned.m8n8.x4.shared.b16 {%0,%1,%2,%3}, [%4];"
                        : "=r"(bk[p][0]), "=r"(bk[p][1]), "=r"(bk[p][2]), "=r"(bk[p][3])
                        : "r"(addr));
                }
#pragma unroll
                for (int j = 0; j < 8; j++) {
                    uint32_t b0 = bk[j >> 1][(j & 1) * 2];
                    uint32_t b1 = bk[j >> 1][(j & 1) * 2 + 1];
                    asm volatile(
                        "mma.sync.aligned.m16n8k16.row.col.f32.f16.f16.f32 "
                        "{%0,%1,%2,%3}, {%4,%5,%6,%7}, {%8,%9}, {%0,%1,%2,%3};"
                        : "+f"(s[j][0]), "+f"(s[j][1]), "+f"(s[j][2]), "+f"(s[j][3])
                        : "r"(qf[t][0]), "r"(qf[t][1]), "r"(qf[t][2]), "r"(qf[t][3]),
                          "r"(b0), "r"(b1));
                }
            }

            // ---- scale + causal mask + online softmax ----
            const bool need_mask = (k0 + 63 > wq0);
            float rmax0 = -1e30f, rmax1 = -1e30f;
#pragma unroll
            for (int j = 0; j < 8; j++) {
#pragma unroll
                for (int e = 0; e < 2; e++) {
                    float v0 = s[j][e]     * 0.125f;
                    float v1 = s[j][2 + e] * 0.125f;
                    if (need_mask) {
                        int col = k0 + j * 8 + 2 * c + e;
                        if (col > wq0 + r)     v0 = -1e30f;
                        if (col > wq0 + r + 8) v1 = -1e30f;
                    }
                    s[j][e] = v0; s[j][2 + e] = v1;
                    rmax0 = fmaxf(rmax0, v0);
                    rmax1 = fmaxf(rmax1, v1);
                }
            }
            rmax0 = fmaxf(rmax0, __shfl_xor_sync(0xffffffffu, rmax0, 1));
            rmax0 = fmaxf(rmax0, __shfl_xor_sync(0xffffffffu, rmax0, 2));
            rmax1 = fmaxf(rmax1, __shfl_xor_sync(0xffffffffu, rmax1, 1));
            rmax1 = fmaxf(rmax1, __shfl_xor_sync(0xffffffffu, rmax1, 2));

            float mn0 = fmaxf(m0, rmax0), mn1 = fmaxf(m1, rmax1);
            float corr0 = __expf(m0 - mn0), corr1 = __expf(m1 - mn1);
            m0 = mn0; m1 = mn1;

            float ls0 = 0.f, ls1 = 0.f;
#pragma unroll
            for (int j = 0; j < 8; j++) {
                s[j][0] = __expf(s[j][0] - mn0);
                s[j][1] = __expf(s[j][1] - mn0);
                s[j][2] = __expf(s[j][2] - mn1);
                s[j][3] = __expf(s[j][3] - mn1);
                ls0 += s[j][0] + s[j][1];
                ls1 += s[j][2] + s[j][3];
            }
            l0 = l0 * corr0 + ls0;
            l1 = l1 * corr1 + ls1;
#pragma unroll
            for (int j = 0; j < 8; j++) {
                o[j][0] *= corr0; o[j][1] *= corr0;
                o[j][2] *= corr1; o[j][3] *= corr1;
            }

            // ---- O += P @ V (fp16) ----
#pragma unroll
            for (int kk = 0; kk < 4; kk++) {
                uint32_t a0 = pack_half2(s[2*kk][0],   s[2*kk][1]);
                uint32_t a1 = pack_half2(s[2*kk][2],   s[2*kk][3]);
                uint32_t a2 = pack_half2(s[2*kk+1][0], s[2*kk+1][1]);
                uint32_t a3 = pack_half2(s[2*kk+1][2], s[2*kk+1][3]);
#pragma unroll
                for (int jj = 0; jj < 4; jj++) {
                    uint32_t addr = sVs + (uint32_t)buf * (ABK * VSTR * 2)
                        + (uint32_t)((kk * 16 + (lane & 15)) * VSTR
                                     + jj * 16 + (lane >> 4) * 8) * 2;
                    uint32_t v0, v1, v2, v3;
                    asm volatile(
                        "ldmatrix.sync.aligned.m8n8.x4.trans.shared.b16 {%0,%1,%2,%3}, [%4];"
                        : "=r"(v0), "=r"(v1), "=r"(v2), "=r"(v3) : "r"(addr));
                    asm volatile(
                        "mma.sync.aligned.m16n8k16.row.col.f32.f16.f16.f32 "
                        "{%0,%1,%2,%3}, {%4,%5,%6,%7}, {%8,%9}, {%0,%1,%2,%3};"
                        : "+f"(o[2*jj][0]), "+f"(o[2*jj][1]), "+f"(o[2*jj][2]), "+f"(o[2*jj][3])
                        : "r"(a0), "r"(a1), "r"(a2), "r"(a3), "r"(v0), "r"(v1));
                    asm volatile(
                        "mma.sync.aligned.m16n8k16.row.col.f32.f16.f16.f32 "
                        "{%0,%1,%2,%3}, {%4,%5,%6,%7}, {%8,%9}, {%0,%1,%2,%3};"
                        : "+f"(o[2*jj+1][0]), "+f"(o[2*jj+1][1]), "+f"(o[2*jj+1][2]), "+f"(o[2*jj+1][3])
                        : "r"(a0), "r"(a1), "r"(a2), "r"(a3), "r"(v2), "r"(v3));
                }
            }
        }
        __syncthreads();
        buf ^= 1;
    }

    l0 += __shfl_xor_sync(0xffffffffu, l0, 1);
    l0 += __shfl_xor_sync(0xffffffffu, l0, 2);
    l1 += __shfl_xor_sync(0xffffffffu, l1, 1);
    l1 += __shfl_xor_sync(0xffffffffu, l1, 2);
    const float inv0 = 1.f / l0, inv1 = 1.f / l1;

    __half* o0p = OH + ((size_t)(b * Ss) + wq0 + r) * Dd + h * HD;
    __half* o1p = o0p + 8 * (size_t)Dd;
#pragma unroll
    for (int j = 0; j < 8; j++) {
        int col = j * 8 + 2 * c;
        *(__half2*)&o0p[col] = __floats2half2_rn(o[j][0] * inv0, o[j][1] * inv0);
        *(__half2*)&o1p[col] = __floats2half2_rn(o[j][2] * inv1, o[j][3] * inv1);
    }
}

// ---------------------------------------------------------------------------
// Launch
// ---------------------------------------------------------------------------
extern "C" void kernel_launch(void* const* d_in, const int* in_sizes, int n_in,
                              void* d_out, int out_size)
{
    const float* x       = (const float*)d_in[0];
    const float* Wq      = (const float*)d_in[1];
    const float* Wk      = (const float*)d_in[2];
    const float* Wv      = (const float*)d_in[3];
    const float* Wq_ded  = (const float*)d_in[4];
    const float* Wk_ded  = (const float*)d_in[5];
    const float* Wv_ded  = (const float*)d_in[6];
    const float* Wo      = (const float*)d_in[7];

    float* out_o = (float*)d_out;
    float* out_k = out_o + ELEM;
    float* out_v = out_k + ELEM;

    float  *qbuf = nullptr;
    __half *xh = nullptr, *wth = nullptr, *ah = nullptr;
    __half *qh = nullptr, *kh = nullptr, *vh = nullptr;
    cudaGetSymbolAddress((void**)&qbuf, g_q);
    cudaGetSymbolAddress((void**)&xh,   g_xh);
    cudaGetSymbolAddress((void**)&wth,  g_wth);
    cudaGetSymbolAddress((void**)&ah,   g_ah);
    cudaGetSymbolAddress((void**)&qh,   g_qh);
    cudaGetSymbolAddress((void**)&kh,   g_kh);
    cudaGetSymbolAddress((void**)&vh,   g_vh);
    __half* wtq = wth;
    __half* wtk = wth + (size_t)Dd * Dd;
    __half* wtv = wth + 2 * (size_t)Dd * Dd;
    __half* wto = wth + 3 * (size_t)Dd * Dd;

    cudaFuncSetAttribute(h_gemm_kernel,
                         cudaFuncAttributeMaxDynamicSharedMemorySize, GEMM_SMEM);
    cudaFuncSetAttribute(attn_tc_kernel,
                         cudaFuncAttributeMaxDynamicSharedMemorySize, ATTN_SMEM);

    // 0) x -> fp16; transpose+convert the 4 weight matrices
    cvt_half_kernel<<<2048, 256>>>(x, xh, (int)(ELEM / 4));
    dim3 tg(32, 32), tb(32, 8);
    transpose_h_kernel<<<tg, tb>>>(Wq, wtq);
    transpose_h_kernel<<<tg, tb>>>(Wk, wtk);
    transpose_h_kernel<<<tg, tb>>>(Wv, wtv);
    transpose_h_kernel<<<tg, tb>>>(Wo, wto);

    // 1) fused Q/K/V shared projections; fp32 outputs + fused fp16 copies
    dim3 gg3(Dd / GBN, TOK / GBM, 3);
    h_gemm_kernel<<<gg3, 256, GEMM_SMEM>>>(
        xh, wtq, wtk, wtv, qbuf, out_k, out_v, qh, kh, vh, Dd);

    // 2) dedicated-weight rows (fp32 compute, dual fp32+fp16 writes)
    dim3 dg(16, Nn, 3);
    ded_proj_kernel<<<dg, 256>>>(x, Wq_ded, Wk_ded, Wv_ded,
                                 qbuf, out_k, out_v, qh, kh, vh);

    // 3) fully-fp16 tensor-core causal attention
    dim3 ag(Ss / ABQ, Hh, Bb);
    attn_tc_kernel<<<ag, 256, ATTN_SMEM>>>(qh, kh, vh, ah);

    // 4) output projection (no fp16 copy needed)
    dim3 gg1(Dd / GBN, TOK / GBM, 1);
    h_gemm_kernel<<<gg1, 256, GEMM_SMEM>>>(
        ah, wto, wto, wto, out_o, out_o, out_o,
        (__half*)nullptr, (__half*)nullptr, (__half*)nullptr, Dd);
}